// round 1
// baseline (speedup 1.0000x reference)
#include <cuda_runtime.h>
#include <cstddef>

// Problem constants
#define SEQ   4096
#define DIM   2048
#define NH    16
#define HD    128
#define QKVW  (3 * DIM)   // 6144

// Scratch (device globals: allocation-free per harness rules)
__device__ float g_qkv[(size_t)SEQ * QKVW];   // (S, 3*dim)
__device__ float g_o  [(size_t)SEQ * DIM];    // (S, dim) attention output

// ---------------------------------------------------------------------------
// SGEMM: C[M,N] = A[M,K] @ B[K,N], row-major. M%128==0, N%128==0, K%16==0.
// 128x128 block tile, BK=16, 256 threads, 8x8 per thread.
// ---------------------------------------------------------------------------
__global__ __launch_bounds__(256) void sgemm_kernel(
    const float* __restrict__ A, const float* __restrict__ B,
    float* __restrict__ C, int M, int N, int K)
{
    __shared__ float As[16][132];   // transposed: As[k][m]; pad to cut store conflicts
    __shared__ float Bs[16][128];   // Bs[k][n]

    const int tid = threadIdx.x;
    const int tx  = tid & 15;       // 0..15  -> N direction
    const int ty  = tid >> 4;       // 0..15  -> M direction
    const int bx  = blockIdx.x;     // N tile
    const int by  = blockIdx.y;     // M tile

    const float* Ab = A + (size_t)by * 128 * K;
    const float* Bb = B + (size_t)bx * 128;

    float acc[8][8];
    #pragma unroll
    for (int i = 0; i < 8; i++)
        #pragma unroll
        for (int j = 0; j < 8; j++) acc[i][j] = 0.f;

    for (int kt = 0; kt < K; kt += 16) {
        // Load A tile: 128 rows x 16 cols = 512 float4 slots (2 per thread)
        #pragma unroll
        for (int i = 0; i < 2; i++) {
            int slot = tid + i * 256;
            int row = slot >> 2;          // 0..127
            int c4  = slot & 3;           // 0..3
            float4 v = *(const float4*)(Ab + (size_t)row * K + kt + c4 * 4);
            As[c4 * 4 + 0][row] = v.x;
            As[c4 * 4 + 1][row] = v.y;
            As[c4 * 4 + 2][row] = v.z;
            As[c4 * 4 + 3][row] = v.w;
        }
        // Load B tile: 16 rows x 128 cols = 512 float4 slots
        #pragma unroll
        for (int i = 0; i < 2; i++) {
            int slot = tid + i * 256;
            int row = slot >> 5;          // 0..15
            int c4  = slot & 31;          // 0..31
            *(float4*)(&Bs[row][c4 * 4]) =
                *(const float4*)(Bb + (size_t)(kt + row) * N + c4 * 4);
        }
        __syncthreads();

        #pragma unroll
        for (int k = 0; k < 16; k++) {
            float a[8], b[8];
            *(float4*)(a)     = *(const float4*)(&As[k][ty * 8]);
            *(float4*)(a + 4) = *(const float4*)(&As[k][ty * 8 + 4]);
            *(float4*)(b)     = *(const float4*)(&Bs[k][tx * 8]);
            *(float4*)(b + 4) = *(const float4*)(&Bs[k][tx * 8 + 4]);
            #pragma unroll
            for (int i = 0; i < 8; i++)
                #pragma unroll
                for (int j = 0; j < 8; j++)
                    acc[i][j] += a[i] * b[j];
        }
        __syncthreads();
    }

    float* Cb = C + (size_t)(by * 128 + ty * 8) * N + bx * 128 + tx * 8;
    #pragma unroll
    for (int i = 0; i < 8; i++) {
        *(float4*)(Cb + (size_t)i * N) =
            make_float4(acc[i][0], acc[i][1], acc[i][2], acc[i][3]);
        *(float4*)(Cb + (size_t)i * N + 4) =
            make_float4(acc[i][4], acc[i][5], acc[i][6], acc[i][7]);
    }
}

// ---------------------------------------------------------------------------
// Flash attention (fp32, online softmax). Mask: key j allowed iff j <= i+1.
// Grid: (SEQ/64, NH). Block: 256 threads (16x16 layout).
// Per thread: 4 query rows (ty*4..+3), strided score cols (tx + 16*j),
// O cols (tx + 16*j, j=0..7).
// ---------------------------------------------------------------------------
#define QS_STRIDE 130   // 128 + 2 : keeps float2 stores aligned, reads conflict-free
#define PS_STRIDE 68    // 64 + 4  : makes the two half-warps hit disjoint banks
#define FLASH_SMEM ((3 * 64 * QS_STRIDE + 64 * PS_STRIDE) * 4)  // 117,248 B

__global__ __launch_bounds__(256) void flash_kernel(
    const float* __restrict__ qkv, float* __restrict__ O)
{
    extern __shared__ float sm[];
    float* Qs = sm;
    float* Ks = sm + 64 * QS_STRIDE;
    float* Vs = sm + 2 * 64 * QS_STRIDE;
    float* Ps = sm + 3 * 64 * QS_STRIDE;

    const int tid = threadIdx.x;
    const int tx  = tid & 15;
    const int ty  = tid >> 4;
    const int qb  = blockIdx.x;     // query block (64 rows)
    const int h   = blockIdx.y;     // head
    const float scale = 0.08838834764831845f;   // 1/sqrt(128)

    // Load Q tile: 64 x 128 floats = 4096 float2 slots (16 per thread)
    const float* Qg = qkv + (size_t)(qb * 64) * QKVW + h * HD;
    #pragma unroll
    for (int i = 0; i < 16; i++) {
        int slot = tid + i * 256;
        int r  = slot >> 6;         // 0..63
        int c2 = slot & 63;         // 0..63
        float2 v = *(const float2*)(Qg + (size_t)r * QKVW + c2 * 2);
        *(float2*)(&Qs[r * QS_STRIDE + c2 * 2]) = v;
    }

    float m_i[4], l_i[4], o_acc[4][8];
    #pragma unroll
    for (int i = 0; i < 4; i++) {
        m_i[i] = -1e30f;
        l_i[i] = 0.f;
        #pragma unroll
        for (int j = 0; j < 8; j++) o_acc[i][j] = 0.f;
    }

    const int kb_end = (qb + 1 < 63) ? (qb + 1) : 63;   // last block with any allowed key
    const int qi0 = qb * 64 + ty * 4;

    for (int kb = 0; kb <= kb_end; kb++) {
        __syncthreads();   // previous-iteration smem reads finished
        // Load K and V tiles (each 64x128 -> 16 float2 per thread)
        const float* Kg = qkv + (size_t)(kb * 64) * QKVW + DIM + h * HD;
        const float* Vg = Kg + DIM;
        #pragma unroll
        for (int i = 0; i < 16; i++) {
            int slot = tid + i * 256;
            int r  = slot >> 6;
            int c2 = slot & 63;
            float2 kv = *(const float2*)(Kg + (size_t)r * QKVW + c2 * 2);
            *(float2*)(&Ks[r * QS_STRIDE + c2 * 2]) = kv;
            float2 vv = *(const float2*)(Vg + (size_t)r * QKVW + c2 * 2);
            *(float2*)(&Vs[r * QS_STRIDE + c2 * 2]) = vv;
        }
        __syncthreads();

        // ---- scores: sc[i][j] = Q[qi0+i] . K[kb*64 + tx + 16*j]
        float sc[4][4];
        #pragma unroll
        for (int i = 0; i < 4; i++)
            #pragma unroll
            for (int j = 0; j < 4; j++) sc[i][j] = 0.f;

        #pragma unroll 8
        for (int d = 0; d < 128; d++) {
            float a0 = Qs[(ty * 4 + 0) * QS_STRIDE + d];
            float a1 = Qs[(ty * 4 + 1) * QS_STRIDE + d];
            float a2 = Qs[(ty * 4 + 2) * QS_STRIDE + d];
            float a3 = Qs[(ty * 4 + 3) * QS_STRIDE + d];
            #pragma unroll
            for (int j = 0; j < 4; j++) {
                float b = Ks[(tx + 16 * j) * QS_STRIDE + d];
                sc[0][j] += a0 * b;
                sc[1][j] += a1 * b;
                sc[2][j] += a2 * b;
                sc[3][j] += a3 * b;
            }
        }

        // ---- mask + scale + online softmax
        #pragma unroll
        for (int i = 0; i < 4; i++) {
            const int qi = qi0 + i;
            float v[4];
            float mx = -1e30f;
            #pragma unroll
            for (int j = 0; j < 4; j++) {
                int kj = kb * 64 + tx + 16 * j;
                v[j] = (kj <= qi + 1) ? sc[i][j] * scale : -1e30f;
                mx = fmaxf(mx, v[j]);
            }
            // row-max across the 16 threads sharing this query row
            #pragma unroll
            for (int off = 8; off > 0; off >>= 1)
                mx = fmaxf(mx, __shfl_xor_sync(0xffffffffu, mx, off, 16));

            float newm = fmaxf(m_i[i], mx);
            float f = __expf(m_i[i] - newm);
            m_i[i] = newm;

            float rs = 0.f;
            #pragma unroll
            for (int j = 0; j < 4; j++) {
                float p = __expf(v[j] - newm);
                Ps[(ty * 4 + i) * PS_STRIDE + tx + 16 * j] = p;
                rs += p;
            }
            #pragma unroll
            for (int off = 8; off > 0; off >>= 1)
                rs += __shfl_xor_sync(0xffffffffu, rs, off, 16);

            l_i[i] = l_i[i] * f + rs;
            #pragma unroll
            for (int j = 0; j < 8; j++) o_acc[i][j] *= f;
        }
        __syncthreads();   // Ps visible to the whole row group

        // ---- O += P @ V
        #pragma unroll 8
        for (int k = 0; k < 64; k++) {
            float a0 = Ps[(ty * 4 + 0) * PS_STRIDE + k];
            float a1 = Ps[(ty * 4 + 1) * PS_STRIDE + k];
            float a2 = Ps[(ty * 4 + 2) * PS_STRIDE + k];
            float a3 = Ps[(ty * 4 + 3) * PS_STRIDE + k];
            #pragma unroll
            for (int j = 0; j < 8; j++) {
                float b = Vs[k * QS_STRIDE + tx + 16 * j];
                o_acc[0][j] += a0 * b;
                o_acc[1][j] += a1 * b;
                o_acc[2][j] += a2 * b;
                o_acc[3][j] += a3 * b;
            }
        }
    }

    // ---- epilogue: normalize and store to g_o (S, dim) at head column block
    #pragma unroll
    for (int i = 0; i < 4; i++) {
        float inv = 1.f / l_i[i];
        float* Og = O + (size_t)(qb * 64 + ty * 4 + i) * DIM + h * HD;
        #pragma unroll
        for (int j = 0; j < 8; j++)
            Og[tx + 16 * j] = o_acc[i][j] * inv;
    }
}

// ---------------------------------------------------------------------------
// Launch
// ---------------------------------------------------------------------------
extern "C" void kernel_launch(void* const* d_in, const int* in_sizes, int n_in,
                              void* d_out, int out_size)
{
    const float* x     = (const float*)d_in[0];  // (4096, 2048)
    const float* w_qkv = (const float*)d_in[1];  // (2048, 6144)
    const float* w_o   = (const float*)d_in[2];  // (2048, 2048)
    float* out = (float*)d_out;                  // (4096, 2048)

    float *qkv, *o;
    cudaGetSymbolAddress((void**)&qkv, g_qkv);
    cudaGetSymbolAddress((void**)&o, g_o);

    cudaFuncSetAttribute(flash_kernel,
                         cudaFuncAttributeMaxDynamicSharedMemorySize, FLASH_SMEM);

    // 1) QKV projection: (4096,2048) @ (2048,6144)
    sgemm_kernel<<<dim3(QKVW / 128, SEQ / 128), 256>>>(x, w_qkv, qkv, SEQ, QKVW, DIM);

    // 2) Attention: 64-row query blocks x 16 heads
    flash_kernel<<<dim3(SEQ / 64, NH), 256, FLASH_SMEM>>>(qkv, o);

    // 3) Output projection: (4096,2048) @ (2048,2048)
    sgemm_kernel<<<dim3(DIM / 128, SEQ / 128), 256>>>(o, w_o, out, SEQ, DIM, DIM);
}

// round 3
// speedup vs baseline: 1.7605x; 1.7605x over previous
#include <cuda_runtime.h>
#include <cstdint>
#include <cstddef>

// Problem constants
#define SEQ   4096
#define DIM   2048
#define NH    16
#define HD    128
#define QKVW  (3 * DIM)   // 6144

// Scratch (device globals: allocation-free per harness rules)
__device__ float g_qkv  [(size_t)SEQ * QKVW];   // (S, 3*dim) QKV projection out
__device__ float g_o    [(size_t)SEQ * DIM];    // (S, dim) attention out (tf32-rounded)
__device__ float g_xr   [(size_t)SEQ * DIM];    // x rounded to tf32
__device__ float g_wqkvT[(size_t)QKVW * DIM];   // w_qkv^T rounded (6144, 2048)
__device__ float g_woT  [(size_t)DIM * DIM];    // w_o^T rounded (2048, 2048)

// ===========================================================================
// Helpers
// ===========================================================================
__device__ __forceinline__ uint32_t smem_u32(const void* p) {
    uint32_t a;
    asm("{ .reg .u64 t; cvta.to.shared.u64 t, %1; cvt.u32.u64 %0, t; }"
        : "=r"(a) : "l"(p));
    return a;
}

__device__ __forceinline__ float rna_tf32(float x) {
    uint32_t u;
    asm("cvt.rna.tf32.f32 %0, %1;" : "=r"(u) : "f"(x));
    return __uint_as_float(u);
}

__device__ __forceinline__ void cp_async16(uint32_t dst, const void* src) {
    asm volatile("cp.async.cg.shared.global [%0], [%1], 16;"
                 :: "r"(dst), "l"(src));
}

__device__ __forceinline__ void ldsm4(uint32_t& r0, uint32_t& r1,
                                      uint32_t& r2, uint32_t& r3, uint32_t addr) {
    asm volatile("ldmatrix.sync.aligned.m8n8.x4.shared.b16 {%0,%1,%2,%3}, [%4];"
                 : "=r"(r0), "=r"(r1), "=r"(r2), "=r"(r3) : "r"(addr));
}

__device__ __forceinline__ void mma_tf32(float* c, const uint32_t* a, const uint32_t* b) {
    asm volatile(
        "mma.sync.aligned.m16n8k8.row.col.f32.tf32.tf32.f32 "
        "{%0,%1,%2,%3}, {%4,%5,%6,%7}, {%8,%9}, {%0,%1,%2,%3};"
        : "+f"(c[0]), "+f"(c[1]), "+f"(c[2]), "+f"(c[3])
        : "r"(a[0]), "r"(a[1]), "r"(a[2]), "r"(a[3]), "r"(b[0]), "r"(b[1]));
}

// ===========================================================================
// tf32 mma.sync GEMM: C[M,N] = A[M,K] @ Bt[N,K]^T (both K-major, tf32-rounded)
// 128x128 CTA tile, BK=32, 3-stage cp.async pipeline, 256 threads (8 warps 4x2).
// M%128==0, N%128==0, K%32==0, K/32>=2.
// ===========================================================================
#define BM 128
#define BN 128
#define BK 32
#define GEMM_STAGES 3
#define STAGE_BYTES 32768                 // A 16KB + B 16KB
#define GEMM_SMEM (GEMM_STAGES * STAGE_BYTES)  // 98304

__global__ __launch_bounds__(256) void gemm_tf32_mma(
    const float* __restrict__ A, const float* __restrict__ Bt,
    float* __restrict__ C, int M, int N, int K)
{
    extern __shared__ __align__(1024) char smem[];
    const uint32_t sb = smem_u32(smem);

    const int tid  = threadIdx.x;
    const int lane = tid & 31;
    const int wid  = tid >> 5;
    const int wm   = (wid & 3) * 32;   // warp M offset in tile
    const int wn   = (wid >> 2) * 64;  // warp N offset in tile

    const int m0 = blockIdx.y * BM;
    const int n0 = blockIdx.x * BN;
    const float* Ag = A  + (size_t)m0 * K;
    const float* Bg = Bt + (size_t)n0 * K;
    const int T = K / BK;

    // cp.async slot geometry: 4 slots/thread/matrix; row = s*32 + tid/8, chunk = tid%8
    const int ld_row_base = tid >> 3;
    const int ld_chunk    = tid & 7;

    auto load_stage = [&](int t, int s) {
        if (t < T) {
            const uint32_t baseA = sb + (uint32_t)s * STAGE_BYTES;
            const uint32_t baseB = baseA + 16384;
            const int k0 = t * BK;
            #pragma unroll
            for (int i = 0; i < 4; i++) {
                int row = i * 32 + ld_row_base;
                uint32_t off = (uint32_t)row * 128u + (uint32_t)ld_chunk * 16u;
                off ^= (off >> 3) & 0x70u;                 // SW128 swizzle
                cp_async16(baseA + off, Ag + (size_t)row * K + k0 + ld_chunk * 4);
                cp_async16(baseB + off, Bg + (size_t)row * K + k0 + ld_chunk * 4);
            }
        }
        asm volatile("cp.async.commit_group;" ::: "memory");
    };

    float acc[2][8][4];
    #pragma unroll
    for (int mt = 0; mt < 2; mt++)
        #pragma unroll
        for (int nt = 0; nt < 8; nt++)
            #pragma unroll
            for (int q = 0; q < 4; q++) acc[mt][nt][q] = 0.f;

    load_stage(0, 0);
    load_stage(1, 1);

    // per-thread ldmatrix row/chunk components (tile-relative)
    const int a_row_in16 = (lane & 7) + ((lane >> 3) & 1) * 8;  // 0..15
    const int a_chsel    = lane >> 4;                            // 0/1 -> k quadrant
    const int b_row_in16 = (lane & 7) + (lane >> 4) * 8;         // 0..15
    const int b_chsel    = (lane >> 3) & 1;                      // 0/1 -> k quadrant

    for (int t = 0; t < T; t++) {
        const int s = t % GEMM_STAGES;
        asm volatile("cp.async.wait_group 1;" ::: "memory");
        __syncthreads();

        load_stage(t + 2, (t + 2) % GEMM_STAGES);   // into buffer (t-1)%3, now free

        const uint32_t baseA = sb + (uint32_t)s * STAGE_BYTES;
        const uint32_t baseB = baseA + 16384;

        #pragma unroll
        for (int k8 = 0; k8 < 4; k8++) {
            uint32_t afr[2][4], bfr[4][4];
            #pragma unroll
            for (int mt = 0; mt < 2; mt++) {
                int row = wm + mt * 16 + a_row_in16;
                int ch  = k8 * 2 + a_chsel;
                uint32_t off = (uint32_t)row * 128u + (uint32_t)ch * 16u;
                off ^= (off >> 3) & 0x70u;
                ldsm4(afr[mt][0], afr[mt][1], afr[mt][2], afr[mt][3], baseA + off);
            }
            #pragma unroll
            for (int np = 0; np < 4; np++) {
                int row = wn + np * 16 + b_row_in16;
                int ch  = k8 * 2 + b_chsel;
                uint32_t off = (uint32_t)row * 128u + (uint32_t)ch * 16u;
                off ^= (off >> 3) & 0x70u;
                ldsm4(bfr[np][0], bfr[np][1], bfr[np][2], bfr[np][3], baseB + off);
            }
            #pragma unroll
            for (int mt = 0; mt < 2; mt++)
                #pragma unroll
                for (int nt = 0; nt < 8; nt++) {
                    uint32_t b2[2] = { bfr[nt >> 1][(nt & 1) * 2],
                                       bfr[nt >> 1][(nt & 1) * 2 + 1] };
                    mma_tf32(acc[mt][nt], afr[mt], b2);
                }
        }
    }

    // Epilogue: c0:(g,2t) c1:(g,2t+1) c2:(g+8,2t) c3:(g+8,2t+1)
    const int g = lane >> 2;
    const int tg = lane & 3;
    #pragma unroll
    for (int mt = 0; mt < 2; mt++) {
        int row0 = m0 + wm + mt * 16 + g;
        #pragma unroll
        for (int nt = 0; nt < 8; nt++) {
            int col = n0 + wn + nt * 8 + tg * 2;
            *(float2*)(C + (size_t)row0 * N + col) =
                make_float2(acc[mt][nt][0], acc[mt][nt][1]);
            *(float2*)(C + (size_t)(row0 + 8) * N + col) =
                make_float2(acc[mt][nt][2], acc[mt][nt][3]);
        }
    }
}

// ===========================================================================
// Pre-passes: tf32 rounding and transpose+round
// ===========================================================================
__global__ __launch_bounds__(256) void round_tf32_kernel(
    const float* __restrict__ in, float* __restrict__ out, size_t n4)
{
    size_t i = (size_t)blockIdx.x * blockDim.x + threadIdx.x;
    size_t stride = (size_t)gridDim.x * blockDim.x;
    for (; i < n4; i += stride) {
        float4 v = ((const float4*)in)[i];
        v.x = rna_tf32(v.x); v.y = rna_tf32(v.y);
        v.z = rna_tf32(v.z); v.w = rna_tf32(v.w);
        ((float4*)out)[i] = v;
    }
}

// out[c][r] = rna(in[r][c]); R, C multiples of 32. Block 32x8.
__global__ __launch_bounds__(256) void transpose_rna_kernel(
    const float* __restrict__ in, float* __restrict__ out, int R, int C)
{
    __shared__ float tile[32][33];
    const int bx = blockIdx.x * 32, by = blockIdx.y * 32;
    const int tx = threadIdx.x, ty = threadIdx.y;
    #pragma unroll
    for (int i = 0; i < 32; i += 8)
        tile[ty + i][tx] = in[(size_t)(by + ty + i) * C + bx + tx];
    __syncthreads();
    #pragma unroll
    for (int i = 0; i < 32; i += 8)
        out[(size_t)(bx + ty + i) * R + by + tx] = rna_tf32(tile[tx][ty + i]);
}

// ===========================================================================
// Flash attention (fp32, online softmax). Mask: key j allowed iff j <= i+1.
// Grid: (SEQ/64, NH). Block: 256 threads. Epilogue writes tf32-rounded values.
// ===========================================================================
#define QS_STRIDE 130
#define PS_STRIDE 68
#define FLASH_SMEM ((3 * 64 * QS_STRIDE + 64 * PS_STRIDE) * 4)

__global__ __launch_bounds__(256) void flash_kernel(
    const float* __restrict__ qkv, float* __restrict__ O)
{
    extern __shared__ float sm[];
    float* Qs = sm;
    float* Ks = sm + 64 * QS_STRIDE;
    float* Vs = sm + 2 * 64 * QS_STRIDE;
    float* Ps = sm + 3 * 64 * QS_STRIDE;

    const int tid = threadIdx.x;
    const int tx  = tid & 15;
    const int ty  = tid >> 4;
    const int qb  = blockIdx.x;
    const int h   = blockIdx.y;
    const float scale = 0.08838834764831845f;   // 1/sqrt(128)

    const float* Qg = qkv + (size_t)(qb * 64) * QKVW + h * HD;
    #pragma unroll
    for (int i = 0; i < 16; i++) {
        int slot = tid + i * 256;
        int r  = slot >> 6;
        int c2 = slot & 63;
        float2 v = *(const float2*)(Qg + (size_t)r * QKVW + c2 * 2);
        *(float2*)(&Qs[r * QS_STRIDE + c2 * 2]) = v;
    }

    float m_i[4], l_i[4], o_acc[4][8];
    #pragma unroll
    for (int i = 0; i < 4; i++) {
        m_i[i] = -1e30f;
        l_i[i] = 0.f;
        #pragma unroll
        for (int j = 0; j < 8; j++) o_acc[i][j] = 0.f;
    }

    const int kb_end = (qb + 1 < 63) ? (qb + 1) : 63;
    const int qi0 = qb * 64 + ty * 4;

    for (int kb = 0; kb <= kb_end; kb++) {
        __syncthreads();
        const float* Kg = qkv + (size_t)(kb * 64) * QKVW + DIM + h * HD;
        const float* Vg = Kg + DIM;
        #pragma unroll
        for (int i = 0; i < 16; i++) {
            int slot = tid + i * 256;
            int r  = slot >> 6;
            int c2 = slot & 63;
            float2 kv = *(const float2*)(Kg + (size_t)r * QKVW + c2 * 2);
            *(float2*)(&Ks[r * QS_STRIDE + c2 * 2]) = kv;
            float2 vv = *(const float2*)(Vg + (size_t)r * QKVW + c2 * 2);
            *(float2*)(&Vs[r * QS_STRIDE + c2 * 2]) = vv;
        }
        __syncthreads();

        float sc[4][4];
        #pragma unroll
        for (int i = 0; i < 4; i++)
            #pragma unroll
            for (int j = 0; j < 4; j++) sc[i][j] = 0.f;

        #pragma unroll 8
        for (int d = 0; d < 128; d++) {
            float a0 = Qs[(ty * 4 + 0) * QS_STRIDE + d];
            float a1 = Qs[(ty * 4 + 1) * QS_STRIDE + d];
            float a2 = Qs[(ty * 4 + 2) * QS_STRIDE + d];
            float a3 = Qs[(ty * 4 + 3) * QS_STRIDE + d];
            #pragma unroll
            for (int j = 0; j < 4; j++) {
                float b = Ks[(tx + 16 * j) * QS_STRIDE + d];
                sc[0][j] += a0 * b;
                sc[1][j] += a1 * b;
                sc[2][j] += a2 * b;
                sc[3][j] += a3 * b;
            }
        }

        #pragma unroll
        for (int i = 0; i < 4; i++) {
            const int qi = qi0 + i;
            float v[4];
            float mx = -1e30f;
            #pragma unroll
            for (int j = 0; j < 4; j++) {
                int kj = kb * 64 + tx + 16 * j;
                v[j] = (kj <= qi + 1) ? sc[i][j] * scale : -1e30f;
                mx = fmaxf(mx, v[j]);
            }
            #pragma unroll
            for (int off = 8; off > 0; off >>= 1)
                mx = fmaxf(mx, __shfl_xor_sync(0xffffffffu, mx, off, 16));

            float newm = fmaxf(m_i[i], mx);
            float f = __expf(m_i[i] - newm);
            m_i[i] = newm;

            float rs = 0.f;
            #pragma unroll
            for (int j = 0; j < 4; j++) {
                float p = __expf(v[j] - newm);
                Ps[(ty * 4 + i) * PS_STRIDE + tx + 16 * j] = p;
                rs += p;
            }
            #pragma unroll
            for (int off = 8; off > 0; off >>= 1)
                rs += __shfl_xor_sync(0xffffffffu, rs, off, 16);

            l_i[i] = l_i[i] * f + rs;
            #pragma unroll
            for (int j = 0; j < 8; j++) o_acc[i][j] *= f;
        }
        __syncthreads();

        #pragma unroll 8
        for (int k = 0; k < 64; k++) {
            float a0 = Ps[(ty * 4 + 0) * PS_STRIDE + k];
            float a1 = Ps[(ty * 4 + 1) * PS_STRIDE + k];
            float a2 = Ps[(ty * 4 + 2) * PS_STRIDE + k];
            float a3 = Ps[(ty * 4 + 3) * PS_STRIDE + k];
            #pragma unroll
            for (int j = 0; j < 8; j++) {
                float b = Vs[k * QS_STRIDE + tx + 16 * j];
                o_acc[0][j] += a0 * b;
                o_acc[1][j] += a1 * b;
                o_acc[2][j] += a2 * b;
                o_acc[3][j] += a3 * b;
            }
        }
    }

    // epilogue: normalize, round to tf32 (GEMM2 consumes as tf32), store
    #pragma unroll
    for (int i = 0; i < 4; i++) {
        float inv = 1.f / l_i[i];
        float* Og = O + (size_t)(qb * 64 + ty * 4 + i) * DIM + h * HD;
        #pragma unroll
        for (int j = 0; j < 8; j++)
            Og[tx + 16 * j] = rna_tf32(o_acc[i][j] * inv);
    }
}

// ===========================================================================
// Launch
// ===========================================================================
extern "C" void kernel_launch(void* const* d_in, const int* in_sizes, int n_in,
                              void* d_out, int out_size)
{
    const float* x     = (const float*)d_in[0];  // (4096, 2048)
    const float* w_qkv = (const float*)d_in[1];  // (2048, 6144)
    const float* w_o   = (const float*)d_in[2];  // (2048, 2048)
    float* out = (float*)d_out;                  // (4096, 2048)

    float *qkv, *o, *xr, *wqkvT, *woT;
    cudaGetSymbolAddress((void**)&qkv,   g_qkv);
    cudaGetSymbolAddress((void**)&o,     g_o);
    cudaGetSymbolAddress((void**)&xr,    g_xr);
    cudaGetSymbolAddress((void**)&wqkvT, g_wqkvT);
    cudaGetSymbolAddress((void**)&woT,   g_woT);

    cudaFuncSetAttribute(gemm_tf32_mma,
                         cudaFuncAttributeMaxDynamicSharedMemorySize, GEMM_SMEM);
    cudaFuncSetAttribute(flash_kernel,
                         cudaFuncAttributeMaxDynamicSharedMemorySize, FLASH_SMEM);

    // 0a) round x to tf32
    round_tf32_kernel<<<4096, 256>>>(x, xr, (size_t)SEQ * DIM / 4);
    // 0b) transpose+round weights to K-major
    transpose_rna_kernel<<<dim3(QKVW / 32, DIM / 32), dim3(32, 8)>>>(w_qkv, wqkvT, DIM, QKVW);
    transpose_rna_kernel<<<dim3(DIM / 32, DIM / 32), dim3(32, 8)>>>(w_o, woT, DIM, DIM);

    // 1) QKV projection (tf32 mma): (4096,2048) @ (2048,6144)
    gemm_tf32_mma<<<dim3(QKVW / 128, SEQ / 128), 256, GEMM_SMEM>>>(xr, wqkvT, qkv, SEQ, QKVW, DIM);

    // 2) Attention (fp32)
    flash_kernel<<<dim3(SEQ / 64, NH), 256, FLASH_SMEM>>>(qkv, o);

    // 3) Output projection (tf32 mma): (4096,2048) @ (2048,2048)
    gemm_tf32_mma<<<dim3(DIM / 128, SEQ / 128), 256, GEMM_SMEM>>>(o, woT, out, SEQ, DIM, DIM);
}

// round 4
// speedup vs baseline: 4.3539x; 2.4732x over previous
#include <cuda_runtime.h>
#include <cstdint>
#include <cstddef>

// Problem constants
#define SEQ   4096
#define DIM   2048
#define NH    16
#define HD    128
#define QKVW  (3 * DIM)   // 6144

// Scratch (device globals: allocation-free per harness rules)
__device__ float g_qkv  [(size_t)SEQ * QKVW];   // (S, 3*dim), tf32-rounded
__device__ float g_o    [(size_t)SEQ * DIM];    // (S, dim) attention out (tf32-rounded)
__device__ float g_xr   [(size_t)SEQ * DIM];    // x rounded to tf32
__device__ float g_wqkvT[(size_t)QKVW * DIM];   // w_qkv^T rounded (6144, 2048)
__device__ float g_woT  [(size_t)DIM * DIM];    // w_o^T rounded (2048, 2048)
__device__ float g_vT   [(size_t)DIM * SEQ];    // V transposed: [h*128+d][s]

// ===========================================================================
// Helpers
// ===========================================================================
__device__ __forceinline__ uint32_t smem_u32(const void* p) {
    uint32_t a;
    asm("{ .reg .u64 t; cvta.to.shared.u64 t, %1; cvt.u32.u64 %0, t; }"
        : "=r"(a) : "l"(p));
    return a;
}

__device__ __forceinline__ float rna_tf32(float x) {
    uint32_t u;
    asm("cvt.rna.tf32.f32 %0, %1;" : "=r"(u) : "f"(x));
    return __uint_as_float(u);
}

__device__ __forceinline__ void cp_async16(uint32_t dst, const void* src) {
    asm volatile("cp.async.cg.shared.global [%0], [%1], 16;"
                 :: "r"(dst), "l"(src));
}

__device__ __forceinline__ void ldsm4(uint32_t& r0, uint32_t& r1,
                                      uint32_t& r2, uint32_t& r3, uint32_t addr) {
    asm volatile("ldmatrix.sync.aligned.m8n8.x4.shared.b16 {%0,%1,%2,%3}, [%4];"
                 : "=r"(r0), "=r"(r1), "=r"(r2), "=r"(r3) : "r"(addr));
}

__device__ __forceinline__ void mma_tf32(float* c, const uint32_t* a, const uint32_t* b) {
    asm volatile(
        "mma.sync.aligned.m16n8k8.row.col.f32.tf32.tf32.f32 "
        "{%0,%1,%2,%3}, {%4,%5,%6,%7}, {%8,%9}, {%0,%1,%2,%3};"
        : "+f"(c[0]), "+f"(c[1]), "+f"(c[2]), "+f"(c[3])
        : "r"(a[0]), "r"(a[1]), "r"(a[2]), "r"(a[3]), "r"(b[0]), "r"(b[1]));
}

__device__ __forceinline__ void sts_v2(uint32_t addr, float a, float b) {
    asm volatile("st.shared.v2.f32 [%0], {%1,%2};" :: "r"(addr), "f"(a), "f"(b));
}

// swizzled smem address: row of RS bytes, 16B chunk c16, XOR low3 with row&7
__device__ __forceinline__ uint32_t swz(uint32_t base, int row, int c16, int rs_bytes) {
    return base + (uint32_t)row * (uint32_t)rs_bytes
                + ((uint32_t)(c16 ^ (row & 7)) << 4);
}

// ===========================================================================
// tf32 mma.sync GEMM: C[M,N] = A[M,K] @ Bt[N,K]^T (both K-major, tf32-rounded)
// 128x128 CTA tile, BK=32, 3-stage cp.async pipeline, 256 threads (8 warps 4x2).
// ROUND: rna-round C on store.
// ===========================================================================
#define BM 128
#define BN 128
#define BK 32
#define GEMM_STAGES 3
#define STAGE_BYTES 32768
#define GEMM_SMEM (GEMM_STAGES * STAGE_BYTES)  // 98304

template<int ROUND>
__global__ __launch_bounds__(256) void gemm_tf32_mma(
    const float* __restrict__ A, const float* __restrict__ Bt,
    float* __restrict__ C, int M, int N, int K)
{
    extern __shared__ __align__(1024) char smem[];
    const uint32_t sb = smem_u32(smem);

    const int tid  = threadIdx.x;
    const int lane = tid & 31;
    const int wid  = tid >> 5;
    const int wm   = (wid & 3) * 32;
    const int wn   = (wid >> 2) * 64;

    const int m0 = blockIdx.y * BM;
    const int n0 = blockIdx.x * BN;
    const float* Ag = A  + (size_t)m0 * K;
    const float* Bg = Bt + (size_t)n0 * K;
    const int T = K / BK;

    const int ld_row_base = tid >> 3;
    const int ld_chunk    = tid & 7;

    auto load_stage = [&](int t, int s) {
        if (t < T) {
            const uint32_t baseA = sb + (uint32_t)s * STAGE_BYTES;
            const uint32_t baseB = baseA + 16384;
            const int k0 = t * BK;
            #pragma unroll
            for (int i = 0; i < 4; i++) {
                int row = i * 32 + ld_row_base;
                cp_async16(swz(baseA, row, ld_chunk, 128),
                           Ag + (size_t)row * K + k0 + ld_chunk * 4);
                cp_async16(swz(baseB, row, ld_chunk, 128),
                           Bg + (size_t)row * K + k0 + ld_chunk * 4);
            }
        }
        asm volatile("cp.async.commit_group;" ::: "memory");
    };

    float acc[2][8][4];
    #pragma unroll
    for (int mt = 0; mt < 2; mt++)
        #pragma unroll
        for (int nt = 0; nt < 8; nt++)
            #pragma unroll
            for (int q = 0; q < 4; q++) acc[mt][nt][q] = 0.f;

    load_stage(0, 0);
    load_stage(1, 1);

    const int a_row_in16 = (lane & 7) + ((lane >> 3) & 1) * 8;
    const int a_chsel    = lane >> 4;
    const int b_row_in16 = (lane & 7) + (lane >> 4) * 8;
    const int b_chsel    = (lane >> 3) & 1;

    for (int t = 0; t < T; t++) {
        const int s = t % GEMM_STAGES;
        asm volatile("cp.async.wait_group 1;" ::: "memory");
        __syncthreads();

        load_stage(t + 2, (t + 2) % GEMM_STAGES);

        const uint32_t baseA = sb + (uint32_t)s * STAGE_BYTES;
        const uint32_t baseB = baseA + 16384;

        #pragma unroll
        for (int k8 = 0; k8 < 4; k8++) {
            uint32_t afr[2][4], bfr[4][4];
            #pragma unroll
            for (int mt = 0; mt < 2; mt++)
                ldsm4(afr[mt][0], afr[mt][1], afr[mt][2], afr[mt][3],
                      swz(baseA, wm + mt * 16 + a_row_in16, k8 * 2 + a_chsel, 128));
            #pragma unroll
            for (int np = 0; np < 4; np++)
                ldsm4(bfr[np][0], bfr[np][1], bfr[np][2], bfr[np][3],
                      swz(baseB, wn + np * 16 + b_row_in16, k8 * 2 + b_chsel, 128));
            #pragma unroll
            for (int mt = 0; mt < 2; mt++)
                #pragma unroll
                for (int nt = 0; nt < 8; nt++) {
                    uint32_t b2[2] = { bfr[nt >> 1][(nt & 1) * 2],
                                       bfr[nt >> 1][(nt & 1) * 2 + 1] };
                    mma_tf32(acc[mt][nt], afr[mt], b2);
                }
        }
    }

    const int g = lane >> 2;
    const int tg = lane & 3;
    #pragma unroll
    for (int mt = 0; mt < 2; mt++) {
        int row0 = m0 + wm + mt * 16 + g;
        #pragma unroll
        for (int nt = 0; nt < 8; nt++) {
            int col = n0 + wn + nt * 8 + tg * 2;
            float c0 = acc[mt][nt][0], c1 = acc[mt][nt][1];
            float c2 = acc[mt][nt][2], c3 = acc[mt][nt][3];
            if (ROUND) {
                c0 = rna_tf32(c0); c1 = rna_tf32(c1);
                c2 = rna_tf32(c2); c3 = rna_tf32(c3);
            }
            *(float2*)(C + (size_t)row0 * N + col) = make_float2(c0, c1);
            *(float2*)(C + (size_t)(row0 + 8) * N + col) = make_float2(c2, c3);
        }
    }
}

// ===========================================================================
// Pre-passes
// ===========================================================================
__global__ __launch_bounds__(256) void round_tf32_kernel(
    const float* __restrict__ in, float* __restrict__ out, size_t n4)
{
    size_t i = (size_t)blockIdx.x * blockDim.x + threadIdx.x;
    size_t stride = (size_t)gridDim.x * blockDim.x;
    for (; i < n4; i += stride) {
        float4 v = ((const float4*)in)[i];
        v.x = rna_tf32(v.x); v.y = rna_tf32(v.y);
        v.z = rna_tf32(v.z); v.w = rna_tf32(v.w);
        ((float4*)out)[i] = v;
    }
}

// out[c][r] = rna(in[r][c]); R, C multiples of 32. Block 32x8.
__global__ __launch_bounds__(256) void transpose_rna_kernel(
    const float* __restrict__ in, float* __restrict__ out, int R, int C)
{
    __shared__ float tile[32][33];
    const int bx = blockIdx.x * 32, by = blockIdx.y * 32;
    const int tx = threadIdx.x, ty = threadIdx.y;
    #pragma unroll
    for (int i = 0; i < 32; i += 8)
        tile[ty + i][tx] = in[(size_t)(by + ty + i) * C + bx + tx];
    __syncthreads();
    #pragma unroll
    for (int i = 0; i < 32; i += 8)
        out[(size_t)(bx + ty + i) * R + by + tx] = rna_tf32(tile[tx][ty + i]);
}

// V transpose: g_vT[c][s] = qkv[s][2*DIM + c], c in [0,2048), s in [0,4096)
__global__ __launch_bounds__(256) void v_transpose_kernel(
    const float* __restrict__ qkv, float* __restrict__ vT)
{
    __shared__ float tile[32][33];
    const int bx = blockIdx.x * 32;   // c block
    const int by = blockIdx.y * 32;   // s block
    const int tx = threadIdx.x, ty = threadIdx.y;
    #pragma unroll
    for (int i = 0; i < 32; i += 8)
        tile[ty + i][tx] = qkv[(size_t)(by + ty + i) * QKVW + 2 * DIM + bx + tx];
    __syncthreads();
    #pragma unroll
    for (int i = 0; i < 32; i += 8)
        vT[(size_t)(bx + ty + i) * SEQ + by + tx] = tile[tx][ty + i];
}

// ===========================================================================
// Flash attention with tf32 mma.sync.
// Block: 256 threads (8 warps), per block: 128 queries x 1 head.
// Iterates 64-key tiles; mask j <= i+1. K/V double buffered.
// smem: [KS0 32K][VTS0 32K][KS1 32K][VTS1 32K][PS 32K] = 160KB
// ===========================================================================
#define FLASH_SMEM (160 * 1024)

__global__ __launch_bounds__(256, 1) void flash_mma_kernel(
    const float* __restrict__ qkv, const float* __restrict__ vT,
    float* __restrict__ O)
{
    extern __shared__ __align__(1024) char smem[];
    const uint32_t sb = smem_u32(smem);
    const uint32_t KS0 = sb, VTS0 = sb + 32768;
    const uint32_t KS1 = sb + 65536, VTS1 = sb + 98304;
    const uint32_t PS  = sb + 131072;

    const int tid  = threadIdx.x;
    const int lane = tid & 31;
    const int wid  = tid >> 5;
    const int qb   = 31 - blockIdx.x;   // heavy blocks first
    const int h    = blockIdx.y;
    const float scale = 0.08838834764831845f;   // 1/sqrt(128)

    const int a_row = (lane & 7) + ((lane >> 3) & 1) * 8;
    const int a_ch  = lane >> 4;
    const int b_row = (lane & 7) + (lane >> 4) * 8;
    const int b_ch  = (lane >> 3) & 1;
    const int g     = lane >> 2;
    const int tg    = lane & 3;

    // ---- Stage Q tile (128 x 128 floats, 512B rows) into [KS0..KS1) region
    {
        const float* Qg = qkv + (size_t)(qb * 128) * QKVW + h * HD;
        #pragma unroll
        for (int i = 0; i < 16; i++) {
            int slot = i * 256 + tid;
            int r = slot >> 5, c = slot & 31;
            cp_async16(swz(sb, r, c, 512), Qg + (size_t)r * QKVW + c * 4);
        }
        asm volatile("cp.async.commit_group;" ::: "memory");
        asm volatile("cp.async.wait_group 0;" ::: "memory");
        __syncthreads();
    }
    uint32_t qf[16][4];
    #pragma unroll
    for (int kk = 0; kk < 16; kk++)
        ldsm4(qf[kk][0], qf[kk][1], qf[kk][2], qf[kk][3],
              swz(sb, wid * 16 + a_row, kk * 2 + a_ch, 512));
    __syncthreads();   // extraction done before K/V overwrite stage 0

    float oacc[16][4];
    #pragma unroll
    for (int nt = 0; nt < 16; nt++)
        #pragma unroll
        for (int q = 0; q < 4; q++) oacc[nt][q] = 0.f;
    float m0 = -1e30f, m1 = -1e30f, l0 = 0.f, l1 = 0.f;

    const int kb_end = min(2 * qb + 2, 63);

    auto load_kv = [&](int kb, int s) {
        const uint32_t KSb  = s ? KS1 : KS0;
        const uint32_t VTSb = s ? VTS1 : VTS0;
        const float* Kg = qkv + (size_t)(kb * 64) * QKVW + DIM + h * HD;
        const float* Vg = vT + (size_t)(h * HD) * SEQ + kb * 64;
        #pragma unroll
        for (int i = 0; i < 8; i++) {
            int slot = i * 256 + tid;
            int r = slot >> 5, c = slot & 31;            // 64 rows x 32 chunks
            cp_async16(swz(KSb, r, c, 512), Kg + (size_t)r * QKVW + c * 4);
        }
        #pragma unroll
        for (int i = 0; i < 8; i++) {
            int slot = i * 256 + tid;
            int r = slot >> 4, c = slot & 15;            // 128 rows x 16 chunks
            cp_async16(swz(VTSb, r, c, 256), Vg + (size_t)r * SEQ + c * 4);
        }
        asm volatile("cp.async.commit_group;" ::: "memory");
    };

    load_kv(0, 0);

    const int qi0 = qb * 128 + wid * 16;

    for (int kb = 0; kb <= kb_end; kb++) {
        const int s = kb & 1;
        const uint32_t KSb  = s ? KS1 : KS0;
        const uint32_t VTSb = s ? VTS1 : VTS0;

        asm volatile("cp.async.wait_group 0;" ::: "memory");
        __syncthreads();
        if (kb < kb_end) load_kv(kb + 1, s ^ 1);

        // ---- S = Q @ K^T  (m16 per warp, n64, k128)
        float sacc[8][4];
        #pragma unroll
        for (int nt = 0; nt < 8; nt++)
            #pragma unroll
            for (int q = 0; q < 4; q++) sacc[nt][q] = 0.f;

        #pragma unroll
        for (int k8 = 0; k8 < 16; k8++) {
            uint32_t bfr[4][4];
            #pragma unroll
            for (int np = 0; np < 4; np++)
                ldsm4(bfr[np][0], bfr[np][1], bfr[np][2], bfr[np][3],
                      swz(KSb, np * 16 + b_row, k8 * 2 + b_ch, 512));
            #pragma unroll
            for (int nt = 0; nt < 8; nt++) {
                uint32_t b2[2] = { bfr[nt >> 1][(nt & 1) * 2],
                                   bfr[nt >> 1][(nt & 1) * 2 + 1] };
                mma_tf32(sacc[nt], qf[k8], b2);
            }
        }

        // ---- online softmax (rows qi0+g and qi0+g+8)
        const int row0 = qi0 + g, row1 = qi0 + g + 8;
        float mx0 = -1e30f, mx1 = -1e30f;
        #pragma unroll
        for (int nt = 0; nt < 8; nt++) {
            #pragma unroll
            for (int c = 0; c < 2; c++) {
                int kj = kb * 64 + nt * 8 + tg * 2 + c;
                float v0 = (kj <= row0 + 1) ? sacc[nt][c] * scale : -1e30f;
                float v1 = (kj <= row1 + 1) ? sacc[nt][c + 2] * scale : -1e30f;
                sacc[nt][c] = v0; sacc[nt][c + 2] = v1;
                mx0 = fmaxf(mx0, v0); mx1 = fmaxf(mx1, v1);
            }
        }
        mx0 = fmaxf(mx0, __shfl_xor_sync(0xffffffffu, mx0, 1));
        mx0 = fmaxf(mx0, __shfl_xor_sync(0xffffffffu, mx0, 2));
        mx1 = fmaxf(mx1, __shfl_xor_sync(0xffffffffu, mx1, 1));
        mx1 = fmaxf(mx1, __shfl_xor_sync(0xffffffffu, mx1, 2));

        float newm0 = fmaxf(m0, mx0), newm1 = fmaxf(m1, mx1);
        float f0 = __expf(m0 - newm0), f1 = __expf(m1 - newm1);
        m0 = newm0; m1 = newm1;

        float rs0 = 0.f, rs1 = 0.f;
        #pragma unroll
        for (int nt = 0; nt < 8; nt++) {
            #pragma unroll
            for (int c = 0; c < 2; c++) {
                float p0 = __expf(sacc[nt][c] - newm0);
                float p1 = __expf(sacc[nt][c + 2] - newm1);
                sacc[nt][c] = p0; sacc[nt][c + 2] = p1;
                rs0 += p0; rs1 += p1;
            }
        }
        rs0 += __shfl_xor_sync(0xffffffffu, rs0, 1);
        rs0 += __shfl_xor_sync(0xffffffffu, rs0, 2);
        rs1 += __shfl_xor_sync(0xffffffffu, rs1, 1);
        rs1 += __shfl_xor_sync(0xffffffffu, rs1, 2);
        l0 = l0 * f0 + rs0;
        l1 = l1 * f1 + rs1;

        #pragma unroll
        for (int nt = 0; nt < 16; nt++) {
            oacc[nt][0] *= f0; oacc[nt][1] *= f0;
            oacc[nt][2] *= f1; oacc[nt][3] *= f1;
        }

        // ---- store P (rna-rounded) to PS: rows 256B, paired float2
        {
            const int r0 = wid * 16 + g, r1 = r0 + 8;
            #pragma unroll
            for (int nt = 0; nt < 8; nt++) {
                int c16 = nt * 2 + (tg >> 1);
                uint32_t byte_in = (uint32_t)((tg & 1) * 8);
                sts_v2(swz(PS, r0, c16, 256) + byte_in,
                       rna_tf32(sacc[nt][0]), rna_tf32(sacc[nt][1]));
                sts_v2(swz(PS, r1, c16, 256) + byte_in,
                       rna_tf32(sacc[nt][2]), rna_tf32(sacc[nt][3]));
            }
        }
        __syncthreads();

        // ---- O += P @ V  (m16 per warp, n128, k64)
        #pragma unroll
        for (int k8 = 0; k8 < 8; k8++) {
            uint32_t afr[4];
            ldsm4(afr[0], afr[1], afr[2], afr[3],
                  swz(PS, wid * 16 + a_row, k8 * 2 + a_ch, 256));
            #pragma unroll
            for (int np = 0; np < 8; np++) {
                uint32_t bfr[4];
                ldsm4(bfr[0], bfr[1], bfr[2], bfr[3],
                      swz(VTSb, np * 16 + b_row, k8 * 2 + b_ch, 256));
                uint32_t b2a[2] = { bfr[0], bfr[1] };
                uint32_t b2b[2] = { bfr[2], bfr[3] };
                mma_tf32(oacc[np * 2 + 0], afr, b2a);
                mma_tf32(oacc[np * 2 + 1], afr, b2b);
            }
        }
        // next-iteration entry sync protects PS and VTS reuse
    }

    // ---- epilogue: normalize, rna-round (GEMM2 consumes as tf32)
    const float inv0 = 1.f / l0, inv1 = 1.f / l1;
    const int row0 = qb * 128 + wid * 16 + g;
    float* Og = O + (size_t)row0 * DIM + h * HD;
    #pragma unroll
    for (int nt = 0; nt < 16; nt++) {
        int col = nt * 8 + tg * 2;
        *(float2*)(Og + col) =
            make_float2(rna_tf32(oacc[nt][0] * inv0), rna_tf32(oacc[nt][1] * inv0));
        *(float2*)(Og + (size_t)8 * DIM + col) =
            make_float2(rna_tf32(oacc[nt][2] * inv1), rna_tf32(oacc[nt][3] * inv1));
    }
}

// ===========================================================================
// Launch
// ===========================================================================
extern "C" void kernel_launch(void* const* d_in, const int* in_sizes, int n_in,
                              void* d_out, int out_size)
{
    const float* x     = (const float*)d_in[0];  // (4096, 2048)
    const float* w_qkv = (const float*)d_in[1];  // (2048, 6144)
    const float* w_o   = (const float*)d_in[2];  // (2048, 2048)
    float* out = (float*)d_out;                  // (4096, 2048)

    float *qkv, *o, *xr, *wqkvT, *woT, *vT;
    cudaGetSymbolAddress((void**)&qkv,   g_qkv);
    cudaGetSymbolAddress((void**)&o,     g_o);
    cudaGetSymbolAddress((void**)&xr,    g_xr);
    cudaGetSymbolAddress((void**)&wqkvT, g_wqkvT);
    cudaGetSymbolAddress((void**)&woT,   g_woT);
    cudaGetSymbolAddress((void**)&vT,    g_vT);

    cudaFuncSetAttribute(gemm_tf32_mma<1>,
                         cudaFuncAttributeMaxDynamicSharedMemorySize, GEMM_SMEM);
    cudaFuncSetAttribute(gemm_tf32_mma<0>,
                         cudaFuncAttributeMaxDynamicSharedMemorySize, GEMM_SMEM);
    cudaFuncSetAttribute(flash_mma_kernel,
                         cudaFuncAttributeMaxDynamicSharedMemorySize, FLASH_SMEM);

    // 0) round x; transpose+round weights
    round_tf32_kernel<<<4096, 256>>>(x, xr, (size_t)SEQ * DIM / 4);
    transpose_rna_kernel<<<dim3(QKVW / 32, DIM / 32), dim3(32, 8)>>>(w_qkv, wqkvT, DIM, QKVW);
    transpose_rna_kernel<<<dim3(DIM / 32, DIM / 32), dim3(32, 8)>>>(w_o, woT, DIM, DIM);

    // 1) QKV projection (tf32 mma, rounded output)
    gemm_tf32_mma<1><<<dim3(QKVW / 128, SEQ / 128), 256, GEMM_SMEM>>>(
        xr, wqkvT, qkv, SEQ, QKVW, DIM);

    // 1b) transpose V per head: g_vT[h*128+d][s]
    v_transpose_kernel<<<dim3(DIM / 32, SEQ / 32), dim3(32, 8)>>>(qkv, vT);

    // 2) Attention (tf32 mma flash)
    flash_mma_kernel<<<dim3(SEQ / 128, NH), 256, FLASH_SMEM>>>(qkv, vT, o);

    // 3) Output projection (tf32 mma)
    gemm_tf32_mma<0><<<dim3(DIM / 128, SEQ / 128), 256, GEMM_SMEM>>>(
        o, woT, out, SEQ, DIM, DIM);
}

// round 5
// speedup vs baseline: 4.3892x; 1.0081x over previous
#include <cuda_runtime.h>
#include <cstdint>
#include <cstddef>

// Problem constants
#define SEQ   4096
#define DIM   2048
#define NH    16
#define HD    128
#define QKVW  (3 * DIM)   // 6144

// Scratch (device globals: allocation-free per harness rules)
__device__ float g_qkv  [(size_t)SEQ * QKVW];   // (S, 3*dim), tf32-rounded
__device__ float g_o    [(size_t)SEQ * DIM];    // (S, dim) attention out (tf32-rounded)
__device__ float g_xr   [(size_t)SEQ * DIM];    // x rounded to tf32
__device__ float g_wqkvT[(size_t)QKVW * DIM];   // w_qkv^T rounded (6144, 2048)
__device__ float g_woT  [(size_t)DIM * DIM];    // w_o^T rounded (2048, 2048)
__device__ float g_vT   [(size_t)DIM * SEQ];    // V transposed: [h*128+d][s]

// ===========================================================================
// Helpers
// ===========================================================================
__device__ __forceinline__ uint32_t smem_u32(const void* p) {
    uint32_t a;
    asm("{ .reg .u64 t; cvta.to.shared.u64 t, %1; cvt.u32.u64 %0, t; }"
        : "=r"(a) : "l"(p));
    return a;
}

__device__ __forceinline__ float rna_tf32(float x) {
    uint32_t u;
    asm("cvt.rna.tf32.f32 %0, %1;" : "=r"(u) : "f"(x));
    return __uint_as_float(u);
}

__device__ __forceinline__ void cp_async16(uint32_t dst, const void* src) {
    asm volatile("cp.async.cg.shared.global [%0], [%1], 16;"
                 :: "r"(dst), "l"(src));
}

__device__ __forceinline__ void ldsm4(uint32_t& r0, uint32_t& r1,
                                      uint32_t& r2, uint32_t& r3, uint32_t addr) {
    asm volatile("ldmatrix.sync.aligned.m8n8.x4.shared.b16 {%0,%1,%2,%3}, [%4];"
                 : "=r"(r0), "=r"(r1), "=r"(r2), "=r"(r3) : "r"(addr));
}

__device__ __forceinline__ void mma_tf32(float* c, const uint32_t* a, const uint32_t* b) {
    asm volatile(
        "mma.sync.aligned.m16n8k8.row.col.f32.tf32.tf32.f32 "
        "{%0,%1,%2,%3}, {%4,%5,%6,%7}, {%8,%9}, {%0,%1,%2,%3};"
        : "+f"(c[0]), "+f"(c[1]), "+f"(c[2]), "+f"(c[3])
        : "r"(a[0]), "r"(a[1]), "r"(a[2]), "r"(a[3]), "r"(b[0]), "r"(b[1]));
}

__device__ __forceinline__ void sts_v2(uint32_t addr, float a, float b) {
    asm volatile("st.shared.v2.f32 [%0], {%1,%2};" :: "r"(addr), "f"(a), "f"(b));
}

// swizzled smem address: row of RS bytes, 16B chunk c16, XOR low3 with row&7
__device__ __forceinline__ uint32_t swz(uint32_t base, int row, int c16, int rs_bytes) {
    return base + (uint32_t)row * (uint32_t)rs_bytes
                + ((uint32_t)(c16 ^ (row & 7)) << 4);
}

// ===========================================================================
// tf32 mma.sync GEMM: C[M,N] = A[M,K] @ Bt[N,K]^T (both K-major, tf32-rounded)
// 128x128 CTA tile, BK=32, 3-stage cp.async pipeline, 256 threads (8 warps 4x2).
// ROUND: rna-round C on store.
// ===========================================================================
#define BM 128
#define BN 128
#define BK 32
#define GEMM_STAGES 3
#define STAGE_BYTES 32768
#define GEMM_SMEM (GEMM_STAGES * STAGE_BYTES)  // 98304

template<int ROUND>
__global__ __launch_bounds__(256) void gemm_tf32_mma(
    const float* __restrict__ A, const float* __restrict__ Bt,
    float* __restrict__ C, int M, int N, int K)
{
    extern __shared__ __align__(1024) char smem[];
    const uint32_t sb = smem_u32(smem);

    const int tid  = threadIdx.x;
    const int lane = tid & 31;
    const int wid  = tid >> 5;
    const int wm   = (wid & 3) * 32;
    const int wn   = (wid >> 2) * 64;

    const int m0 = blockIdx.y * BM;
    const int n0 = blockIdx.x * BN;
    const float* Ag = A  + (size_t)m0 * K;
    const float* Bg = Bt + (size_t)n0 * K;
    const int T = K / BK;

    const int ld_row_base = tid >> 3;
    const int ld_chunk    = tid & 7;

    auto load_stage = [&](int t, int s) {
        if (t < T) {
            const uint32_t baseA = sb + (uint32_t)s * STAGE_BYTES;
            const uint32_t baseB = baseA + 16384;
            const int k0 = t * BK;
            #pragma unroll
            for (int i = 0; i < 4; i++) {
                int row = i * 32 + ld_row_base;
                cp_async16(swz(baseA, row, ld_chunk, 128),
                           Ag + (size_t)row * K + k0 + ld_chunk * 4);
                cp_async16(swz(baseB, row, ld_chunk, 128),
                           Bg + (size_t)row * K + k0 + ld_chunk * 4);
            }
        }
        asm volatile("cp.async.commit_group;" ::: "memory");
    };

    float acc[2][8][4];
    #pragma unroll
    for (int mt = 0; mt < 2; mt++)
        #pragma unroll
        for (int nt = 0; nt < 8; nt++)
            #pragma unroll
            for (int q = 0; q < 4; q++) acc[mt][nt][q] = 0.f;

    load_stage(0, 0);
    load_stage(1, 1);

    const int a_row_in16 = (lane & 7) + ((lane >> 3) & 1) * 8;
    const int a_chsel    = lane >> 4;
    const int b_row_in16 = (lane & 7) + (lane >> 4) * 8;
    const int b_chsel    = (lane >> 3) & 1;

    for (int t = 0; t < T; t++) {
        const int s = t % GEMM_STAGES;
        asm volatile("cp.async.wait_group 1;" ::: "memory");
        __syncthreads();

        load_stage(t + 2, (t + 2) % GEMM_STAGES);

        const uint32_t baseA = sb + (uint32_t)s * STAGE_BYTES;
        const uint32_t baseB = baseA + 16384;

        #pragma unroll
        for (int k8 = 0; k8 < 4; k8++) {
            uint32_t afr[2][4], bfr[4][4];
            #pragma unroll
            for (int mt = 0; mt < 2; mt++)
                ldsm4(afr[mt][0], afr[mt][1], afr[mt][2], afr[mt][3],
                      swz(baseA, wm + mt * 16 + a_row_in16, k8 * 2 + a_chsel, 128));
            #pragma unroll
            for (int np = 0; np < 4; np++)
                ldsm4(bfr[np][0], bfr[np][1], bfr[np][2], bfr[np][3],
                      swz(baseB, wn + np * 16 + b_row_in16, k8 * 2 + b_chsel, 128));
            #pragma unroll
            for (int mt = 0; mt < 2; mt++)
                #pragma unroll
                for (int nt = 0; nt < 8; nt++) {
                    uint32_t b2[2] = { bfr[nt >> 1][(nt & 1) * 2],
                                       bfr[nt >> 1][(nt & 1) * 2 + 1] };
                    mma_tf32(acc[mt][nt], afr[mt], b2);
                }
        }
    }

    const int g = lane >> 2;
    const int tg = lane & 3;
    #pragma unroll
    for (int mt = 0; mt < 2; mt++) {
        int row0 = m0 + wm + mt * 16 + g;
        #pragma unroll
        for (int nt = 0; nt < 8; nt++) {
            int col = n0 + wn + nt * 8 + tg * 2;
            float c0 = acc[mt][nt][0], c1 = acc[mt][nt][1];
            float c2 = acc[mt][nt][2], c3 = acc[mt][nt][3];
            if (ROUND) {
                c0 = rna_tf32(c0); c1 = rna_tf32(c1);
                c2 = rna_tf32(c2); c3 = rna_tf32(c3);
            }
            *(float2*)(C + (size_t)row0 * N + col) = make_float2(c0, c1);
            *(float2*)(C + (size_t)(row0 + 8) * N + col) = make_float2(c2, c3);
        }
    }
}

// ===========================================================================
// Pre-passes
// ===========================================================================
__global__ __launch_bounds__(256) void round_tf32_kernel(
    const float* __restrict__ in, float* __restrict__ out, size_t n4)
{
    size_t i = (size_t)blockIdx.x * blockDim.x + threadIdx.x;
    size_t stride = (size_t)gridDim.x * blockDim.x;
    for (; i < n4; i += stride) {
        float4 v = ((const float4*)in)[i];
        v.x = rna_tf32(v.x); v.y = rna_tf32(v.y);
        v.z = rna_tf32(v.z); v.w = rna_tf32(v.w);
        ((float4*)out)[i] = v;
    }
}

// out[c][r] = rna(in[r][c]); R, C multiples of 32. Block 32x8.
__global__ __launch_bounds__(256) void transpose_rna_kernel(
    const float* __restrict__ in, float* __restrict__ out, int R, int C)
{
    __shared__ float tile[32][33];
    const int bx = blockIdx.x * 32, by = blockIdx.y * 32;
    const int tx = threadIdx.x, ty = threadIdx.y;
    #pragma unroll
    for (int i = 0; i < 32; i += 8)
        tile[ty + i][tx] = in[(size_t)(by + ty + i) * C + bx + tx];
    __syncthreads();
    #pragma unroll
    for (int i = 0; i < 32; i += 8)
        out[(size_t)(bx + ty + i) * R + by + tx] = rna_tf32(tile[tx][ty + i]);
}

// V transpose: g_vT[c][s] = qkv[s][2*DIM + c], c in [0,2048), s in [0,4096)
__global__ __launch_bounds__(256) void v_transpose_kernel(
    const float* __restrict__ qkv, float* __restrict__ vT)
{
    __shared__ float tile[32][33];
    const int bx = blockIdx.x * 32;   // c block
    const int by = blockIdx.y * 32;   // s block
    const int tx = threadIdx.x, ty = threadIdx.y;
    #pragma unroll
    for (int i = 0; i < 32; i += 8)
        tile[ty + i][tx] = qkv[(size_t)(by + ty + i) * QKVW + 2 * DIM + bx + tx];
    __syncthreads();
    #pragma unroll
    for (int i = 0; i < 32; i += 8)
        vT[(size_t)(bx + ty + i) * SEQ + by + tx] = tile[tx][ty + i];
}

// ===========================================================================
// Flash attention with tf32 mma.sync.
// Block: 256 threads (8 warps), per block: 128 queries x 1 head.
// Iterates 64-key tiles; mask j <= i+1. K/V double buffered with SPLIT
// commit groups: S-mma waits only on K; V awaited just before PV.
// smem: [KS0 32K][VTS0 32K][KS1 32K][VTS1 32K][PS 32K] = 160KB
// ===========================================================================
#define FLASH_SMEM (160 * 1024)

__global__ __launch_bounds__(256, 1) void flash_mma_kernel(
    const float* __restrict__ qkv, const float* __restrict__ vT,
    float* __restrict__ O)
{
    extern __shared__ __align__(1024) char smem[];
    const uint32_t sb = smem_u32(smem);
    const uint32_t KS0 = sb, VTS0 = sb + 32768;
    const uint32_t KS1 = sb + 65536, VTS1 = sb + 98304;
    const uint32_t PS  = sb + 131072;

    const int tid  = threadIdx.x;
    const int lane = tid & 31;
    const int wid  = tid >> 5;
    const int qb   = 31 - blockIdx.x;   // heavy blocks first
    const int h    = blockIdx.y;
    const float scale = 0.08838834764831845f;   // 1/sqrt(128)

    const int a_row = (lane & 7) + ((lane >> 3) & 1) * 8;
    const int a_ch  = lane >> 4;
    const int b_row = (lane & 7) + (lane >> 4) * 8;
    const int b_ch  = (lane >> 3) & 1;
    const int g     = lane >> 2;
    const int tg    = lane & 3;

    // ---- Stage Q tile (128 x 128 floats, 512B rows) into [KS0..KS1) region
    {
        const float* Qg = qkv + (size_t)(qb * 128) * QKVW + h * HD;
        #pragma unroll
        for (int i = 0; i < 16; i++) {
            int slot = i * 256 + tid;
            int r = slot >> 5, c = slot & 31;
            cp_async16(swz(sb, r, c, 512), Qg + (size_t)r * QKVW + c * 4);
        }
        asm volatile("cp.async.commit_group;" ::: "memory");
        asm volatile("cp.async.wait_group 0;" ::: "memory");
        __syncthreads();
    }
    uint32_t qf[16][4];
    #pragma unroll
    for (int kk = 0; kk < 16; kk++)
        ldsm4(qf[kk][0], qf[kk][1], qf[kk][2], qf[kk][3],
              swz(sb, wid * 16 + a_row, kk * 2 + a_ch, 512));
    __syncthreads();   // extraction done before K/V overwrite stage 0

    float oacc[16][4];
    #pragma unroll
    for (int nt = 0; nt < 16; nt++)
        #pragma unroll
        for (int q = 0; q < 4; q++) oacc[nt][q] = 0.f;
    float m0 = -1e30f, m1 = -1e30f, l0 = 0.f, l1 = 0.f;

    const int kb_end = min(2 * qb + 2, 63);

    // Loads K tile (own commit group), then V tile (own commit group).
    auto load_kv = [&](int kb, int s) {
        const uint32_t KSb  = s ? KS1 : KS0;
        const uint32_t VTSb = s ? VTS1 : VTS0;
        const float* Kg = qkv + (size_t)(kb * 64) * QKVW + DIM + h * HD;
        const float* Vg = vT + (size_t)(h * HD) * SEQ + kb * 64;
        #pragma unroll
        for (int i = 0; i < 8; i++) {
            int slot = i * 256 + tid;
            int r = slot >> 5, c = slot & 31;            // 64 rows x 32 chunks
            cp_async16(swz(KSb, r, c, 512), Kg + (size_t)r * QKVW + c * 4);
        }
        asm volatile("cp.async.commit_group;" ::: "memory");   // K group
        #pragma unroll
        for (int i = 0; i < 8; i++) {
            int slot = i * 256 + tid;
            int r = slot >> 4, c = slot & 15;            // 128 rows x 16 chunks
            cp_async16(swz(VTSb, r, c, 256), Vg + (size_t)r * SEQ + c * 4);
        }
        asm volatile("cp.async.commit_group;" ::: "memory");   // V group
    };

    load_kv(0, 0);

    const int qi0 = qb * 128 + wid * 16;

    for (int kb = 0; kb <= kb_end; kb++) {
        const int s = kb & 1;
        const uint32_t KSb  = s ? KS1 : KS0;
        const uint32_t VTSb = s ? VTS1 : VTS0;

        // K_kb ready (V_kb may still be in flight)
        asm volatile("cp.async.wait_group 1;" ::: "memory");
        __syncthreads();   // all warps done with buffers from iter kb-1
        if (kb < kb_end) load_kv(kb + 1, s ^ 1);

        // ---- S = Q @ K^T  (m16 per warp, n64, k128)
        float sacc[8][4];
        #pragma unroll
        for (int nt = 0; nt < 8; nt++)
            #pragma unroll
            for (int q = 0; q < 4; q++) sacc[nt][q] = 0.f;

        #pragma unroll
        for (int k8 = 0; k8 < 16; k8++) {
            uint32_t bfr[4][4];
            #pragma unroll
            for (int np = 0; np < 4; np++)
                ldsm4(bfr[np][0], bfr[np][1], bfr[np][2], bfr[np][3],
                      swz(KSb, np * 16 + b_row, k8 * 2 + b_ch, 512));
            #pragma unroll
            for (int nt = 0; nt < 8; nt++) {
                uint32_t b2[2] = { bfr[nt >> 1][(nt & 1) * 2],
                                   bfr[nt >> 1][(nt & 1) * 2 + 1] };
                mma_tf32(sacc[nt], qf[k8], b2);
            }
        }

        // ---- online softmax (rows qi0+g and qi0+g+8)
        const int row0 = qi0 + g, row1 = qi0 + g + 8;
        float mx0 = -1e30f, mx1 = -1e30f;
        #pragma unroll
        for (int nt = 0; nt < 8; nt++) {
            #pragma unroll
            for (int c = 0; c < 2; c++) {
                int kj = kb * 64 + nt * 8 + tg * 2 + c;
                float v0 = (kj <= row0 + 1) ? sacc[nt][c] * scale : -1e30f;
                float v1 = (kj <= row1 + 1) ? sacc[nt][c + 2] * scale : -1e30f;
                sacc[nt][c] = v0; sacc[nt][c + 2] = v1;
                mx0 = fmaxf(mx0, v0); mx1 = fmaxf(mx1, v1);
            }
        }
        mx0 = fmaxf(mx0, __shfl_xor_sync(0xffffffffu, mx0, 1));
        mx0 = fmaxf(mx0, __shfl_xor_sync(0xffffffffu, mx0, 2));
        mx1 = fmaxf(mx1, __shfl_xor_sync(0xffffffffu, mx1, 1));
        mx1 = fmaxf(mx1, __shfl_xor_sync(0xffffffffu, mx1, 2));

        float newm0 = fmaxf(m0, mx0), newm1 = fmaxf(m1, mx1);
        float f0 = __expf(m0 - newm0), f1 = __expf(m1 - newm1);
        m0 = newm0; m1 = newm1;

        float rs0 = 0.f, rs1 = 0.f;
        #pragma unroll
        for (int nt = 0; nt < 8; nt++) {
            #pragma unroll
            for (int c = 0; c < 2; c++) {
                float p0 = __expf(sacc[nt][c] - newm0);
                float p1 = __expf(sacc[nt][c + 2] - newm1);
                sacc[nt][c] = p0; sacc[nt][c + 2] = p1;
                rs0 += p0; rs1 += p1;
            }
        }

        // ---- store P (rna-rounded) to PS: rows 256B, paired float2.
        // PV A-fragments for warp `wid` come exclusively from PS rows
        // [wid*16, wid*16+16) written by this warp -> __syncwarp suffices.
        {
            const int r0 = wid * 16 + g, r1 = r0 + 8;
            #pragma unroll
            for (int nt = 0; nt < 8; nt++) {
                int c16 = nt * 2 + (tg >> 1);
                uint32_t byte_in = (uint32_t)((tg & 1) * 8);
                sts_v2(swz(PS, r0, c16, 256) + byte_in,
                       rna_tf32(sacc[nt][0]), rna_tf32(sacc[nt][1]));
                sts_v2(swz(PS, r1, c16, 256) + byte_in,
                       rna_tf32(sacc[nt][2]), rna_tf32(sacc[nt][3]));
            }
        }
        __syncwarp();

        // finish softmax bookkeeping / rescale while P stores land & V arrives
        rs0 += __shfl_xor_sync(0xffffffffu, rs0, 1);
        rs0 += __shfl_xor_sync(0xffffffffu, rs0, 2);
        rs1 += __shfl_xor_sync(0xffffffffu, rs1, 1);
        rs1 += __shfl_xor_sync(0xffffffffu, rs1, 2);
        l0 = l0 * f0 + rs0;
        l1 = l1 * f1 + rs1;

        #pragma unroll
        for (int nt = 0; nt < 16; nt++) {
            oacc[nt][0] *= f0; oacc[nt][1] *= f0;
            oacc[nt][2] *= f1; oacc[nt][3] *= f1;
        }

        // V_kb ready (pending groups: at most the two kb+1 groups)
        if (kb < kb_end) asm volatile("cp.async.wait_group 2;" ::: "memory");
        else             asm volatile("cp.async.wait_group 0;" ::: "memory");

        // ---- O += P @ V  (m16 per warp, n128, k64)
        #pragma unroll
        for (int k8 = 0; k8 < 8; k8++) {
            uint32_t afr[4];
            ldsm4(afr[0], afr[1], afr[2], afr[3],
                  swz(PS, wid * 16 + a_row, k8 * 2 + a_ch, 256));
            #pragma unroll
            for (int np = 0; np < 8; np++) {
                uint32_t bfr[4];
                ldsm4(bfr[0], bfr[1], bfr[2], bfr[3],
                      swz(VTSb, np * 16 + b_row, k8 * 2 + b_ch, 256));
                uint32_t b2a[2] = { bfr[0], bfr[1] };
                uint32_t b2b[2] = { bfr[2], bfr[3] };
                mma_tf32(oacc[np * 2 + 0], afr, b2a);
                mma_tf32(oacc[np * 2 + 1], afr, b2b);
            }
        }
        // next-iteration entry sync protects PS and VTS reuse
    }

    // ---- epilogue: normalize, rna-round (GEMM2 consumes as tf32)
    const float inv0 = 1.f / l0, inv1 = 1.f / l1;
    const int row0 = qb * 128 + wid * 16 + g;
    float* Og = O + (size_t)row0 * DIM + h * HD;
    #pragma unroll
    for (int nt = 0; nt < 16; nt++) {
        int col = nt * 8 + tg * 2;
        *(float2*)(Og + col) =
            make_float2(rna_tf32(oacc[nt][0] * inv0), rna_tf32(oacc[nt][1] * inv0));
        *(float2*)(Og + (size_t)8 * DIM + col) =
            make_float2(rna_tf32(oacc[nt][2] * inv1), rna_tf32(oacc[nt][3] * inv1));
    }
}

// ===========================================================================
// Launch
// ===========================================================================
extern "C" void kernel_launch(void* const* d_in, const int* in_sizes, int n_in,
                              void* d_out, int out_size)
{
    const float* x     = (const float*)d_in[0];  // (4096, 2048)
    const float* w_qkv = (const float*)d_in[1];  // (2048, 6144)
    const float* w_o   = (const float*)d_in[2];  // (2048, 2048)
    float* out = (float*)d_out;                  // (4096, 2048)

    float *qkv, *o, *xr, *wqkvT, *woT, *vT;
    cudaGetSymbolAddress((void**)&qkv,   g_qkv);
    cudaGetSymbolAddress((void**)&o,     g_o);
    cudaGetSymbolAddress((void**)&xr,    g_xr);
    cudaGetSymbolAddress((void**)&wqkvT, g_wqkvT);
    cudaGetSymbolAddress((void**)&woT,   g_woT);
    cudaGetSymbolAddress((void**)&vT,    g_vT);

    cudaFuncSetAttribute(gemm_tf32_mma<1>,
                         cudaFuncAttributeMaxDynamicSharedMemorySize, GEMM_SMEM);
    cudaFuncSetAttribute(gemm_tf32_mma<0>,
                         cudaFuncAttributeMaxDynamicSharedMemorySize, GEMM_SMEM);
    cudaFuncSetAttribute(flash_mma_kernel,
                         cudaFuncAttributeMaxDynamicSharedMemorySize, FLASH_SMEM);

    // 0) round x; transpose+round weights
    round_tf32_kernel<<<4096, 256>>>(x, xr, (size_t)SEQ * DIM / 4);
    transpose_rna_kernel<<<dim3(QKVW / 32, DIM / 32), dim3(32, 8)>>>(w_qkv, wqkvT, DIM, QKVW);
    transpose_rna_kernel<<<dim3(DIM / 32, DIM / 32), dim3(32, 8)>>>(w_o, woT, DIM, DIM);

    // 1) QKV projection (tf32 mma, rounded output)
    gemm_tf32_mma<1><<<dim3(QKVW / 128, SEQ / 128), 256, GEMM_SMEM>>>(
        xr, wqkvT, qkv, SEQ, QKVW, DIM);

    // 1b) transpose V per head: g_vT[h*128+d][s]
    v_transpose_kernel<<<dim3(DIM / 32, SEQ / 32), dim3(32, 8)>>>(qkv, vT);

    // 2) Attention (tf32 mma flash)
    flash_mma_kernel<<<dim3(SEQ / 128, NH), 256, FLASH_SMEM>>>(qkv, vT, o);

    // 3) Output projection (tf32 mma)
    gemm_tf32_mma<0><<<dim3(DIM / 128, SEQ / 128), 256, GEMM_SMEM>>>(
        o, woT, out, SEQ, DIM, DIM);
}

// round 6
// speedup vs baseline: 4.3963x; 1.0016x over previous
#include <cuda_runtime.h>
#include <cstdint>
#include <cstddef>

// Problem constants
#define SEQ   4096
#define DIM   2048
#define NH    16
#define HD    128
#define QKVW  (3 * DIM)   // 6144

// Scratch (device globals: allocation-free per harness rules)
__device__ float g_qkv  [(size_t)SEQ * QKVW];   // (S, 3*dim), tf32-rounded
__device__ float g_o    [(size_t)SEQ * DIM];    // (S, dim) attention out (tf32-rounded)
__device__ float g_xr   [(size_t)SEQ * DIM];    // x rounded to tf32
__device__ float g_wqkvT[(size_t)QKVW * DIM];   // w_qkv^T rounded (6144, 2048)
__device__ float g_woT  [(size_t)DIM * DIM];    // w_o^T rounded (2048, 2048)
__device__ float g_vT   [(size_t)DIM * SEQ];    // V transposed: [h*128+d][s]

// ===========================================================================
// Helpers
// ===========================================================================
__device__ __forceinline__ uint32_t smem_u32(const void* p) {
    uint32_t a;
    asm("{ .reg .u64 t; cvta.to.shared.u64 t, %1; cvt.u32.u64 %0, t; }"
        : "=r"(a) : "l"(p));
    return a;
}

__device__ __forceinline__ float rna_tf32(float x) {
    uint32_t u;
    asm("cvt.rna.tf32.f32 %0, %1;" : "=r"(u) : "f"(x));
    return __uint_as_float(u);
}

__device__ __forceinline__ void cp_async16(uint32_t dst, const void* src) {
    asm volatile("cp.async.cg.shared.global [%0], [%1], 16;"
                 :: "r"(dst), "l"(src));
}

__device__ __forceinline__ void ldsm4(uint32_t& r0, uint32_t& r1,
                                      uint32_t& r2, uint32_t& r3, uint32_t addr) {
    asm volatile("ldmatrix.sync.aligned.m8n8.x4.shared.b16 {%0,%1,%2,%3}, [%4];"
                 : "=r"(r0), "=r"(r1), "=r"(r2), "=r"(r3) : "r"(addr));
}

__device__ __forceinline__ void mma_tf32(float* c, const uint32_t* a, const uint32_t* b) {
    asm volatile(
        "mma.sync.aligned.m16n8k8.row.col.f32.tf32.tf32.f32 "
        "{%0,%1,%2,%3}, {%4,%5,%6,%7}, {%8,%9}, {%0,%1,%2,%3};"
        : "+f"(c[0]), "+f"(c[1]), "+f"(c[2]), "+f"(c[3])
        : "r"(a[0]), "r"(a[1]), "r"(a[2]), "r"(a[3]), "r"(b[0]), "r"(b[1]));
}

__device__ __forceinline__ void sts_v2(uint32_t addr, float a, float b) {
    asm volatile("st.shared.v2.f32 [%0], {%1,%2};" :: "r"(addr), "f"(a), "f"(b));
}

// swizzled smem address: row of RS bytes, 16B chunk c16, XOR low3 with row&7
__device__ __forceinline__ uint32_t swz(uint32_t base, int row, int c16, int rs_bytes) {
    return base + (uint32_t)row * (uint32_t)rs_bytes
                + ((uint32_t)(c16 ^ (row & 7)) << 4);
}

// ---- mbarrier primitives (base ISA, no 'a' features) ----
#define MBARRIER_INIT(mbar, cnt) \
    asm volatile("mbarrier.init.shared.b64 [%0], %1;" \
        :: "r"((uint32_t)(mbar)), "r"((uint32_t)(cnt)) : "memory")

#define MBARRIER_ARRIVE(mbar) \
    asm volatile("mbarrier.arrive.shared.b64 _, [%0];" \
        :: "r"((uint32_t)(mbar)) : "memory")

#define CPASYNC_MBAR_ARRIVE(mbar) \
    asm volatile("cp.async.mbarrier.arrive.noinc.shared.b64 [%0];" \
        :: "r"((uint32_t)(mbar)) : "memory")

#define MBARRIER_WAIT_PARITY(mbar, parity) do { \
    uint32_t _m = (uint32_t)(mbar); \
    uint32_t _p = (uint32_t)(parity); \
    uint32_t _done; \
    asm volatile( \
        "{\n\t.reg .pred p;\n\t" \
        "mbarrier.try_wait.parity.acquire.cta.shared::cta.b64 p, [%1], %2;\n\t" \
        "selp.b32 %0, 1, 0, p;\n\t}" \
        : "=r"(_done) : "r"(_m), "r"(_p) : "memory"); \
    if (!_done) { \
        asm volatile( \
            "{\n\t.reg .pred P1;\n\t" \
            "WAIT_LOOP_%=:\n\t" \
            "mbarrier.try_wait.parity.acquire.cta.shared::cta.b64 P1, [%0], %1, 0x989680;\n\t" \
            "@P1 bra.uni WAIT_DONE_%=;\n\t" \
            "bra.uni WAIT_LOOP_%=;\n\t" \
            "WAIT_DONE_%=:\n\t}" \
            :: "r"(_m), "r"(_p) : "memory"); \
    } \
} while (0)

// ===========================================================================
// tf32 mma.sync GEMM: C[M,N] = A[M,K] @ Bt[N,K]^T (both K-major, tf32-rounded)
// 128x128 CTA tile, BK=32, 3-stage cp.async pipeline, 256 threads (8 warps 4x2).
// ROUND: rna-round C on store.
// ===========================================================================
#define BM 128
#define BN 128
#define BK 32
#define GEMM_STAGES 3
#define STAGE_BYTES 32768
#define GEMM_SMEM (GEMM_STAGES * STAGE_BYTES)  // 98304

template<int ROUND>
__global__ __launch_bounds__(256) void gemm_tf32_mma(
    const float* __restrict__ A, const float* __restrict__ Bt,
    float* __restrict__ C, int M, int N, int K)
{
    extern __shared__ __align__(1024) char smem[];
    const uint32_t sb = smem_u32(smem);

    const int tid  = threadIdx.x;
    const int lane = tid & 31;
    const int wid  = tid >> 5;
    const int wm   = (wid & 3) * 32;
    const int wn   = (wid >> 2) * 64;

    const int m0 = blockIdx.y * BM;
    const int n0 = blockIdx.x * BN;
    const float* Ag = A  + (size_t)m0 * K;
    const float* Bg = Bt + (size_t)n0 * K;
    const int T = K / BK;

    const int ld_row_base = tid >> 3;
    const int ld_chunk    = tid & 7;

    auto load_stage = [&](int t, int s) {
        if (t < T) {
            const uint32_t baseA = sb + (uint32_t)s * STAGE_BYTES;
            const uint32_t baseB = baseA + 16384;
            const int k0 = t * BK;
            #pragma unroll
            for (int i = 0; i < 4; i++) {
                int row = i * 32 + ld_row_base;
                cp_async16(swz(baseA, row, ld_chunk, 128),
                           Ag + (size_t)row * K + k0 + ld_chunk * 4);
                cp_async16(swz(baseB, row, ld_chunk, 128),
                           Bg + (size_t)row * K + k0 + ld_chunk * 4);
            }
        }
        asm volatile("cp.async.commit_group;" ::: "memory");
    };

    float acc[2][8][4];
    #pragma unroll
    for (int mt = 0; mt < 2; mt++)
        #pragma unroll
        for (int nt = 0; nt < 8; nt++)
            #pragma unroll
            for (int q = 0; q < 4; q++) acc[mt][nt][q] = 0.f;

    load_stage(0, 0);
    load_stage(1, 1);

    const int a_row_in16 = (lane & 7) + ((lane >> 3) & 1) * 8;
    const int a_chsel    = lane >> 4;
    const int b_row_in16 = (lane & 7) + (lane >> 4) * 8;
    const int b_chsel    = (lane >> 3) & 1;

    for (int t = 0; t < T; t++) {
        const int s = t % GEMM_STAGES;
        asm volatile("cp.async.wait_group 1;" ::: "memory");
        __syncthreads();

        load_stage(t + 2, (t + 2) % GEMM_STAGES);

        const uint32_t baseA = sb + (uint32_t)s * STAGE_BYTES;
        const uint32_t baseB = baseA + 16384;

        #pragma unroll
        for (int k8 = 0; k8 < 4; k8++) {
            uint32_t afr[2][4], bfr[4][4];
            #pragma unroll
            for (int mt = 0; mt < 2; mt++)
                ldsm4(afr[mt][0], afr[mt][1], afr[mt][2], afr[mt][3],
                      swz(baseA, wm + mt * 16 + a_row_in16, k8 * 2 + a_chsel, 128));
            #pragma unroll
            for (int np = 0; np < 4; np++)
                ldsm4(bfr[np][0], bfr[np][1], bfr[np][2], bfr[np][3],
                      swz(baseB, wn + np * 16 + b_row_in16, k8 * 2 + b_chsel, 128));
            #pragma unroll
            for (int mt = 0; mt < 2; mt++)
                #pragma unroll
                for (int nt = 0; nt < 8; nt++) {
                    uint32_t b2[2] = { bfr[nt >> 1][(nt & 1) * 2],
                                       bfr[nt >> 1][(nt & 1) * 2 + 1] };
                    mma_tf32(acc[mt][nt], afr[mt], b2);
                }
        }
    }

    const int g = lane >> 2;
    const int tg = lane & 3;
    #pragma unroll
    for (int mt = 0; mt < 2; mt++) {
        int row0 = m0 + wm + mt * 16 + g;
        #pragma unroll
        for (int nt = 0; nt < 8; nt++) {
            int col = n0 + wn + nt * 8 + tg * 2;
            float c0 = acc[mt][nt][0], c1 = acc[mt][nt][1];
            float c2 = acc[mt][nt][2], c3 = acc[mt][nt][3];
            if (ROUND) {
                c0 = rna_tf32(c0); c1 = rna_tf32(c1);
                c2 = rna_tf32(c2); c3 = rna_tf32(c3);
            }
            *(float2*)(C + (size_t)row0 * N + col) = make_float2(c0, c1);
            *(float2*)(C + (size_t)(row0 + 8) * N + col) = make_float2(c2, c3);
        }
    }
}

// ===========================================================================
// Pre-passes
// ===========================================================================
__global__ __launch_bounds__(256) void round_tf32_kernel(
    const float* __restrict__ in, float* __restrict__ out, size_t n4)
{
    size_t i = (size_t)blockIdx.x * blockDim.x + threadIdx.x;
    size_t stride = (size_t)gridDim.x * blockDim.x;
    for (; i < n4; i += stride) {
        float4 v = ((const float4*)in)[i];
        v.x = rna_tf32(v.x); v.y = rna_tf32(v.y);
        v.z = rna_tf32(v.z); v.w = rna_tf32(v.w);
        ((float4*)out)[i] = v;
    }
}

// out[c][r] = rna(in[r][c]); R, C multiples of 32. Block 32x8.
__global__ __launch_bounds__(256) void transpose_rna_kernel(
    const float* __restrict__ in, float* __restrict__ out, int R, int C)
{
    __shared__ float tile[32][33];
    const int bx = blockIdx.x * 32, by = blockIdx.y * 32;
    const int tx = threadIdx.x, ty = threadIdx.y;
    #pragma unroll
    for (int i = 0; i < 32; i += 8)
        tile[ty + i][tx] = in[(size_t)(by + ty + i) * C + bx + tx];
    __syncthreads();
    #pragma unroll
    for (int i = 0; i < 32; i += 8)
        out[(size_t)(bx + ty + i) * R + by + tx] = rna_tf32(tile[tx][ty + i]);
}

// V transpose: g_vT[c][s] = qkv[s][2*DIM + c]
__global__ __launch_bounds__(256) void v_transpose_kernel(
    const float* __restrict__ qkv, float* __restrict__ vT)
{
    __shared__ float tile[32][33];
    const int bx = blockIdx.x * 32;   // c block
    const int by = blockIdx.y * 32;   // s block
    const int tx = threadIdx.x, ty = threadIdx.y;
    #pragma unroll
    for (int i = 0; i < 32; i += 8)
        tile[ty + i][tx] = qkv[(size_t)(by + ty + i) * QKVW + 2 * DIM + bx + tx];
    __syncthreads();
    #pragma unroll
    for (int i = 0; i < 32; i += 8)
        vT[(size_t)(bx + ty + i) * SEQ + by + tx] = tile[tx][ty + i];
}

// ===========================================================================
// Flash attention with tf32 mma.sync — FREE-RUNNING warps via mbarriers.
// Block: 256 threads (8 warps), per block: 128 queries x 1 head.
// 3 K+V stages of 64KB each (K 64x512B + VT 128x256B), PS 32KB, mbars.
// No __syncthreads in the main loop: full[s]/empty[s] mbarriers (256 arrivals)
// bound warp skew to ~1 iteration so scalar softmax overlaps other warps' mma.
// smem: 3*65536 + 32768 + 64 = 229440 B
// ===========================================================================
#define FLASH_SMEM 229440

__global__ __launch_bounds__(256, 1) void flash_mma_kernel(
    const float* __restrict__ qkv, const float* __restrict__ vT,
    float* __restrict__ O)
{
    extern __shared__ __align__(1024) char smem[];
    const uint32_t sb  = smem_u32(smem);
    const uint32_t PS  = sb + 196608u;           // 32KB P tile
    const uint32_t MB  = sb + 229376u;           // full[s]=MB+8s, empty[s]=MB+24+8s

    const int tid  = threadIdx.x;
    const int lane = tid & 31;
    const int wid  = tid >> 5;
    const int qb   = 31 - blockIdx.x;   // heavy blocks first
    const int h    = blockIdx.y;
    // softmax in exp2 domain: scale2 = (1/sqrt(128)) * log2(e)
    const float scale2 = 0.12751879652672068f;

    const int a_row = (lane & 7) + ((lane >> 3) & 1) * 8;
    const int a_ch  = lane >> 4;
    const int b_row = (lane & 7) + (lane >> 4) * 8;
    const int b_ch  = (lane >> 3) & 1;
    const int g     = lane >> 2;
    const int tg    = lane & 3;

    // ---- Stage Q tile (128 x 128 floats, 512B rows) into stage0+stage1 region
    {
        const float* Qg = qkv + (size_t)(qb * 128) * QKVW + h * HD;
        #pragma unroll
        for (int i = 0; i < 16; i++) {
            int slot = i * 256 + tid;
            int r = slot >> 5, c = slot & 31;
            cp_async16(swz(sb, r, c, 512), Qg + (size_t)r * QKVW + c * 4);
        }
        asm volatile("cp.async.commit_group;" ::: "memory");
        asm volatile("cp.async.wait_group 0;" ::: "memory");
        __syncthreads();
    }
    uint32_t qf[16][4];
    #pragma unroll
    for (int kk = 0; kk < 16; kk++)
        ldsm4(qf[kk][0], qf[kk][1], qf[kk][2], qf[kk][3],
              swz(sb, wid * 16 + a_row, kk * 2 + a_ch, 512));
    __syncthreads();   // Q extraction done before stage buffers are overwritten

    if (tid == 0) {
        #pragma unroll
        for (int s = 0; s < 3; s++) {
            MBARRIER_INIT(MB + 8 * s, 256);        // full[s]
            MBARRIER_INIT(MB + 24 + 8 * s, 256);   // empty[s]
        }
    }
    __syncthreads();

    float oacc[16][4];
    #pragma unroll
    for (int nt = 0; nt < 16; nt++)
        #pragma unroll
        for (int q = 0; q < 4; q++) oacc[nt][q] = 0.f;
    float m0 = -1e30f, m1 = -1e30f, l0 = 0.f, l1 = 0.f;

    const int kb_end = min(2 * qb + 2, 63);   // always >= 2
    const int qi0 = qb * 128 + wid * 16;

    // Load K+V tile t into stage st (16 cp.async per thread, no commit groups)
    auto load_tile = [&](int t, int st) {
        const uint32_t KSb  = sb + (uint32_t)st * 65536u;
        const uint32_t VTSb = KSb + 32768u;
        const float* Kg = qkv + (size_t)(t * 64) * QKVW + DIM + h * HD;
        const float* Vg = vT + (size_t)(h * HD) * SEQ + t * 64;
        #pragma unroll
        for (int i = 0; i < 8; i++) {
            int slot = i * 256 + tid;
            int r = slot >> 5, c = slot & 31;            // 64 rows x 32 chunks
            cp_async16(swz(KSb, r, c, 512), Kg + (size_t)r * QKVW + c * 4);
        }
        #pragma unroll
        for (int i = 0; i < 8; i++) {
            int slot = i * 256 + tid;
            int r = slot >> 4, c = slot & 15;            // 128 rows x 16 chunks
            cp_async16(swz(VTSb, r, c, 256), Vg + (size_t)r * SEQ + c * 4);
        }
    };

    // prologue: tiles 0 and 1 (generation 0 — no empty wait needed)
    load_tile(0, 0); CPASYNC_MBAR_ARRIVE(MB + 0);
    load_tile(1, 1); CPASYNC_MBAR_ARRIVE(MB + 8);

    for (int kb = 0; kb <= kb_end; kb++) {
        // ---- producer: tile kb+2 into stage (kb+2)%3
        {
            const int t = kb + 2;
            if (t <= kb_end) {
                const int st = t % 3;
                if (t >= 3)   // wait consumers of tile t-3 (generation t/3 - 1)
                    MBARRIER_WAIT_PARITY(MB + 24 + 8 * st, (uint32_t)((t / 3 - 1) & 1));
                load_tile(t, st);
                CPASYNC_MBAR_ARRIVE(MB + 8 * st);
            }
        }

        const int s  = kb % 3;
        const int ph = (kb / 3) & 1;
        MBARRIER_WAIT_PARITY(MB + 8 * s, (uint32_t)ph);   // K+V tile kb resident

        // fully-masked for this warp's 16 rows? (first key > max_row+1)
        const bool skipw = (kb * 64 > qi0 + 16);
        if (!skipw) {
            const uint32_t KSb  = sb + (uint32_t)s * 65536u;
            const uint32_t VTSb = KSb + 32768u;

            // ---- S = Q @ K^T  (m16 per warp, n64, k128)
            float sacc[8][4];
            #pragma unroll
            for (int nt = 0; nt < 8; nt++)
                #pragma unroll
                for (int q = 0; q < 4; q++) sacc[nt][q] = 0.f;

            #pragma unroll
            for (int k8 = 0; k8 < 16; k8++) {
                uint32_t bfr[4][4];
                #pragma unroll
                for (int np = 0; np < 4; np++)
                    ldsm4(bfr[np][0], bfr[np][1], bfr[np][2], bfr[np][3],
                          swz(KSb, np * 16 + b_row, k8 * 2 + b_ch, 512));
                #pragma unroll
                for (int nt = 0; nt < 8; nt++) {
                    uint32_t b2[2] = { bfr[nt >> 1][(nt & 1) * 2],
                                       bfr[nt >> 1][(nt & 1) * 2 + 1] };
                    mma_tf32(sacc[nt], qf[k8], b2);
                }
            }

            // ---- online softmax in exp2 domain (rows qi0+g, qi0+g+8)
            const int row0 = qi0 + g, row1 = qi0 + g + 8;
            const bool nomask = (kb * 64 + 63 <= qi0 + 1);   // all keys allowed
            float mx0 = -1e30f, mx1 = -1e30f;
            if (nomask) {
                #pragma unroll
                for (int nt = 0; nt < 8; nt++)
                    #pragma unroll
                    for (int c = 0; c < 2; c++) {
                        float v0 = sacc[nt][c] * scale2;
                        float v1 = sacc[nt][c + 2] * scale2;
                        sacc[nt][c] = v0; sacc[nt][c + 2] = v1;
                        mx0 = fmaxf(mx0, v0); mx1 = fmaxf(mx1, v1);
                    }
            } else {
                #pragma unroll
                for (int nt = 0; nt < 8; nt++)
                    #pragma unroll
                    for (int c = 0; c < 2; c++) {
                        int kj = kb * 64 + nt * 8 + tg * 2 + c;
                        float v0 = (kj <= row0 + 1) ? sacc[nt][c] * scale2 : -1e30f;
                        float v1 = (kj <= row1 + 1) ? sacc[nt][c + 2] * scale2 : -1e30f;
                        sacc[nt][c] = v0; sacc[nt][c + 2] = v1;
                        mx0 = fmaxf(mx0, v0); mx1 = fmaxf(mx1, v1);
                    }
            }
            mx0 = fmaxf(mx0, __shfl_xor_sync(0xffffffffu, mx0, 1));
            mx0 = fmaxf(mx0, __shfl_xor_sync(0xffffffffu, mx0, 2));
            mx1 = fmaxf(mx1, __shfl_xor_sync(0xffffffffu, mx1, 1));
            mx1 = fmaxf(mx1, __shfl_xor_sync(0xffffffffu, mx1, 2));

            float newm0 = fmaxf(m0, mx0), newm1 = fmaxf(m1, mx1);
            float f0 = exp2f(m0 - newm0), f1 = exp2f(m1 - newm1);
            m0 = newm0; m1 = newm1;

            float rs0 = 0.f, rs1 = 0.f;
            #pragma unroll
            for (int nt = 0; nt < 8; nt++)
                #pragma unroll
                for (int c = 0; c < 2; c++) {
                    float p0 = exp2f(sacc[nt][c] - newm0);
                    float p1 = exp2f(sacc[nt][c + 2] - newm1);
                    sacc[nt][c] = p0; sacc[nt][c + 2] = p1;
                    rs0 += p0; rs1 += p1;
                }

            // ---- store P (rna-rounded) to PS (own warp's rows only)
            {
                const int r0 = wid * 16 + g, r1 = r0 + 8;
                #pragma unroll
                for (int nt = 0; nt < 8; nt++) {
                    int c16 = nt * 2 + (tg >> 1);
                    uint32_t byte_in = (uint32_t)((tg & 1) * 8);
                    sts_v2(swz(PS, r0, c16, 256) + byte_in,
                           rna_tf32(sacc[nt][0]), rna_tf32(sacc[nt][1]));
                    sts_v2(swz(PS, r1, c16, 256) + byte_in,
                           rna_tf32(sacc[nt][2]), rna_tf32(sacc[nt][3]));
                }
            }
            __syncwarp();

            rs0 += __shfl_xor_sync(0xffffffffu, rs0, 1);
            rs0 += __shfl_xor_sync(0xffffffffu, rs0, 2);
            rs1 += __shfl_xor_sync(0xffffffffu, rs1, 1);
            rs1 += __shfl_xor_sync(0xffffffffu, rs1, 2);
            l0 = l0 * f0 + rs0;
            l1 = l1 * f1 + rs1;

            #pragma unroll
            for (int nt = 0; nt < 16; nt++) {
                oacc[nt][0] *= f0; oacc[nt][1] *= f0;
                oacc[nt][2] *= f1; oacc[nt][3] *= f1;
            }

            // ---- O += P @ V  (m16 per warp, n128, k64)
            #pragma unroll
            for (int k8 = 0; k8 < 8; k8++) {
                uint32_t afr[4];
                ldsm4(afr[0], afr[1], afr[2], afr[3],
                      swz(PS, wid * 16 + a_row, k8 * 2 + a_ch, 256));
                #pragma unroll
                for (int np = 0; np < 8; np++) {
                    uint32_t bfr[4];
                    ldsm4(bfr[0], bfr[1], bfr[2], bfr[3],
                          swz(VTSb, np * 16 + b_row, k8 * 2 + b_ch, 256));
                    uint32_t b2a[2] = { bfr[0], bfr[1] };
                    uint32_t b2b[2] = { bfr[2], bfr[3] };
                    mma_tf32(oacc[np * 2 + 0], afr, b2a);
                    mma_tf32(oacc[np * 2 + 1], afr, b2b);
                }
            }
        }

        MBARRIER_ARRIVE(MB + 24 + 8 * s);   // done with stage s this generation
    }

    // ---- epilogue: normalize, rna-round (GEMM2 consumes as tf32)
    const float inv0 = 1.f / l0, inv1 = 1.f / l1;
    const int row0 = qb * 128 + wid * 16 + g;
    float* Og = O + (size_t)row0 * DIM + h * HD;
    #pragma unroll
    for (int nt = 0; nt < 16; nt++) {
        int col = nt * 8 + tg * 2;
        *(float2*)(Og + col) =
            make_float2(rna_tf32(oacc[nt][0] * inv0), rna_tf32(oacc[nt][1] * inv0));
        *(float2*)(Og + (size_t)8 * DIM + col) =
            make_float2(rna_tf32(oacc[nt][2] * inv1), rna_tf32(oacc[nt][3] * inv1));
    }
}

// ===========================================================================
// Launch
// ===========================================================================
extern "C" void kernel_launch(void* const* d_in, const int* in_sizes, int n_in,
                              void* d_out, int out_size)
{
    const float* x     = (const float*)d_in[0];  // (4096, 2048)
    const float* w_qkv = (const float*)d_in[1];  // (2048, 6144)
    const float* w_o   = (const float*)d_in[2];  // (2048, 2048)
    float* out = (float*)d_out;                  // (4096, 2048)

    float *qkv, *o, *xr, *wqkvT, *woT, *vT;
    cudaGetSymbolAddress((void**)&qkv,   g_qkv);
    cudaGetSymbolAddress((void**)&o,     g_o);
    cudaGetSymbolAddress((void**)&xr,    g_xr);
    cudaGetSymbolAddress((void**)&wqkvT, g_wqkvT);
    cudaGetSymbolAddress((void**)&woT,   g_woT);
    cudaGetSymbolAddress((void**)&vT,    g_vT);

    cudaFuncSetAttribute(gemm_tf32_mma<1>,
                         cudaFuncAttributeMaxDynamicSharedMemorySize, GEMM_SMEM);
    cudaFuncSetAttribute(gemm_tf32_mma<0>,
                         cudaFuncAttributeMaxDynamicSharedMemorySize, GEMM_SMEM);
    cudaFuncSetAttribute(flash_mma_kernel,
                         cudaFuncAttributeMaxDynamicSharedMemorySize, FLASH_SMEM);

    // 0) round x; transpose+round weights
    round_tf32_kernel<<<4096, 256>>>(x, xr, (size_t)SEQ * DIM / 4);
    transpose_rna_kernel<<<dim3(QKVW / 32, DIM / 32), dim3(32, 8)>>>(w_qkv, wqkvT, DIM, QKVW);
    transpose_rna_kernel<<<dim3(DIM / 32, DIM / 32), dim3(32, 8)>>>(w_o, woT, DIM, DIM);

    // 1) QKV projection (tf32 mma, rounded output)
    gemm_tf32_mma<1><<<dim3(QKVW / 128, SEQ / 128), 256, GEMM_SMEM>>>(
        xr, wqkvT, qkv, SEQ, QKVW, DIM);

    // 1b) transpose V per head: g_vT[h*128+d][s]
    v_transpose_kernel<<<dim3(DIM / 32, SEQ / 32), dim3(32, 8)>>>(qkv, vT);

    // 2) Attention (tf32 mma flash, free-running mbarrier pipeline)
    flash_mma_kernel<<<dim3(SEQ / 128, NH), 256, FLASH_SMEM>>>(qkv, vT, o);

    // 3) Output projection (tf32 mma)
    gemm_tf32_mma<0><<<dim3(DIM / 128, SEQ / 128), 256, GEMM_SMEM>>>(
        o, woT, out, SEQ, DIM, DIM);
}

// round 7
// speedup vs baseline: 7.9122x; 1.7997x over previous
#include <cuda_runtime.h>
#include <cuda_fp16.h>
#include <cstdint>
#include <cstddef>

// Problem constants
#define SEQ   4096
#define DIM   2048
#define NH    16
#define HD    128
#define QKVW  (3 * DIM)   // 6144

// Scratch (device globals: allocation-free per harness rules)
__device__ __half g_qkvh [(size_t)SEQ * QKVW];  // (S, 3*dim) fp16
__device__ __half g_oh   [(size_t)SEQ * DIM];   // attention out fp16
__device__ __half g_xh   [(size_t)SEQ * DIM];   // x fp16
__device__ __half g_wqkvT[(size_t)QKVW * DIM];  // w_qkv^T fp16 (6144, 2048)
__device__ __half g_woT  [(size_t)DIM * DIM];   // w_o^T fp16
__device__ __half g_vTh  [(size_t)DIM * SEQ];   // V^T fp16: [h*128+d][s]

// ===========================================================================
// Helpers
// ===========================================================================
__device__ __forceinline__ uint32_t smem_u32(const void* p) {
    uint32_t a;
    asm("{ .reg .u64 t; cvta.to.shared.u64 t, %1; cvt.u32.u64 %0, t; }"
        : "=r"(a) : "l"(p));
    return a;
}

__device__ __forceinline__ uint32_t pack_h2(float lo, float hi) {
    __half2 h = __floats2half2_rn(lo, hi);
    return *(uint32_t*)&h;
}

__device__ __forceinline__ void cp_async16(uint32_t dst, const void* src) {
    asm volatile("cp.async.cg.shared.global [%0], [%1], 16;"
                 :: "r"(dst), "l"(src));
}

__device__ __forceinline__ void ldsm4(uint32_t& r0, uint32_t& r1,
                                      uint32_t& r2, uint32_t& r3, uint32_t addr) {
    asm volatile("ldmatrix.sync.aligned.m8n8.x4.shared.b16 {%0,%1,%2,%3}, [%4];"
                 : "=r"(r0), "=r"(r1), "=r"(r2), "=r"(r3) : "r"(addr));
}

__device__ __forceinline__ void mma_f16(float* c, const uint32_t* a, const uint32_t* b) {
    asm volatile(
        "mma.sync.aligned.m16n8k16.row.col.f32.f16.f16.f32 "
        "{%0,%1,%2,%3}, {%4,%5,%6,%7}, {%8,%9}, {%0,%1,%2,%3};"
        : "+f"(c[0]), "+f"(c[1]), "+f"(c[2]), "+f"(c[3])
        : "r"(a[0]), "r"(a[1]), "r"(a[2]), "r"(a[3]), "r"(b[0]), "r"(b[1]));
}

// swizzled smem address: row of RS bytes, 16B chunk c16, XOR low3 with row&7
__device__ __forceinline__ uint32_t swz(uint32_t base, int row, int c16, int rs_bytes) {
    return base + (uint32_t)row * (uint32_t)rs_bytes
                + ((uint32_t)(c16 ^ (row & 7)) << 4);
}

// ---- mbarrier primitives (base ISA) ----
#define MBARRIER_INIT(mbar, cnt) \
    asm volatile("mbarrier.init.shared.b64 [%0], %1;" \
        :: "r"((uint32_t)(mbar)), "r"((uint32_t)(cnt)) : "memory")

#define MBARRIER_ARRIVE(mbar) \
    asm volatile("mbarrier.arrive.shared.b64 _, [%0];" \
        :: "r"((uint32_t)(mbar)) : "memory")

#define CPASYNC_MBAR_ARRIVE(mbar) \
    asm volatile("cp.async.mbarrier.arrive.noinc.shared.b64 [%0];" \
        :: "r"((uint32_t)(mbar)) : "memory")

#define MBARRIER_WAIT_PARITY(mbar, parity) do { \
    uint32_t _m = (uint32_t)(mbar); \
    uint32_t _p = (uint32_t)(parity); \
    uint32_t _done; \
    asm volatile( \
        "{\n\t.reg .pred p;\n\t" \
        "mbarrier.try_wait.parity.acquire.cta.shared::cta.b64 p, [%1], %2;\n\t" \
        "selp.b32 %0, 1, 0, p;\n\t}" \
        : "=r"(_done) : "r"(_m), "r"(_p) : "memory"); \
    if (!_done) { \
        asm volatile( \
            "{\n\t.reg .pred P1;\n\t" \
            "WAIT_LOOP_%=:\n\t" \
            "mbarrier.try_wait.parity.acquire.cta.shared::cta.b64 P1, [%0], %1, 0x989680;\n\t" \
            "@P1 bra.uni WAIT_DONE_%=;\n\t" \
            "bra.uni WAIT_LOOP_%=;\n\t" \
            "WAIT_DONE_%=:\n\t}" \
            :: "r"(_m), "r"(_p) : "memory"); \
    } \
} while (0)

// ===========================================================================
// fp16 mma GEMM: C[M,N] = A[M,K] @ Bt[N,K]^T (half, K-major).
// 128x128 CTA tile, BK=64 (128B rows), 3-stage cp.async, 256 threads (4x2 warps).
// OUT_HALF: store half, else float.
// ===========================================================================
#define GEMM_STAGES 3
#define STAGE_BYTES 32768            // A 16KB + B 16KB
#define GEMM_SMEM (GEMM_STAGES * STAGE_BYTES)  // 98304

template<int OUT_HALF>
__global__ __launch_bounds__(256) void gemm_f16_mma(
    const __half* __restrict__ A, const __half* __restrict__ Bt,
    void* __restrict__ Cv, int M, int N, int K)
{
    extern __shared__ __align__(1024) char smem[];
    const uint32_t sb = smem_u32(smem);

    const int tid  = threadIdx.x;
    const int lane = tid & 31;
    const int wid  = tid >> 5;
    const int wm   = (wid & 3) * 32;
    const int wn   = (wid >> 2) * 64;

    const int m0 = blockIdx.y * 128;
    const int n0 = blockIdx.x * 128;
    const __half* Ag = A  + (size_t)m0 * K;
    const __half* Bg = Bt + (size_t)n0 * K;
    const int T = K / 64;

    auto load_stage = [&](int t, int s) {
        if (t < T) {
            const uint32_t baseA = sb + (uint32_t)s * STAGE_BYTES;
            const uint32_t baseB = baseA + 16384;
            const int k0 = t * 64;
            #pragma unroll
            for (int i = 0; i < 4; i++) {
                int slot = i * 256 + tid;
                int row = slot >> 3, c = slot & 7;       // 128 rows x 8 chunks
                cp_async16(swz(baseA, row, c, 128),
                           Ag + (size_t)row * K + k0 + c * 8);
                cp_async16(swz(baseB, row, c, 128),
                           Bg + (size_t)row * K + k0 + c * 8);
            }
        }
        asm volatile("cp.async.commit_group;" ::: "memory");
    };

    float acc[2][8][4];
    #pragma unroll
    for (int mt = 0; mt < 2; mt++)
        #pragma unroll
        for (int nt = 0; nt < 8; nt++)
            #pragma unroll
            for (int q = 0; q < 4; q++) acc[mt][nt][q] = 0.f;

    load_stage(0, 0);
    load_stage(1, 1);

    const int a_row16 = lane & 15;
    const int a_ch    = lane >> 4;
    const int b_row   = (lane & 7) + (lane >> 4) * 8;
    const int b_ch    = (lane >> 3) & 1;

    for (int t = 0; t < T; t++) {
        const int s = t % GEMM_STAGES;
        asm volatile("cp.async.wait_group 1;" ::: "memory");
        __syncthreads();

        load_stage(t + 2, (t + 2) % GEMM_STAGES);

        const uint32_t baseA = sb + (uint32_t)s * STAGE_BYTES;
        const uint32_t baseB = baseA + 16384;

        #pragma unroll
        for (int k16 = 0; k16 < 4; k16++) {
            uint32_t afr[2][4], bfr[4][4];
            #pragma unroll
            for (int mt = 0; mt < 2; mt++)
                ldsm4(afr[mt][0], afr[mt][1], afr[mt][2], afr[mt][3],
                      swz(baseA, wm + mt * 16 + a_row16, k16 * 2 + a_ch, 128));
            #pragma unroll
            for (int np = 0; np < 4; np++)
                ldsm4(bfr[np][0], bfr[np][1], bfr[np][2], bfr[np][3],
                      swz(baseB, wn + np * 16 + b_row, k16 * 2 + b_ch, 128));
            #pragma unroll
            for (int mt = 0; mt < 2; mt++)
                #pragma unroll
                for (int nt = 0; nt < 8; nt++) {
                    uint32_t b2[2] = { bfr[nt >> 1][(nt & 1) * 2],
                                       bfr[nt >> 1][(nt & 1) * 2 + 1] };
                    mma_f16(acc[mt][nt], afr[mt], b2);
                }
        }
    }

    const int g = lane >> 2;
    const int tg = lane & 3;
    #pragma unroll
    for (int mt = 0; mt < 2; mt++) {
        int row0 = m0 + wm + mt * 16 + g;
        #pragma unroll
        for (int nt = 0; nt < 8; nt++) {
            int col = n0 + wn + nt * 8 + tg * 2;
            if (OUT_HALF) {
                __half* C = (__half*)Cv;
                *(uint32_t*)(C + (size_t)row0 * N + col) =
                    pack_h2(acc[mt][nt][0], acc[mt][nt][1]);
                *(uint32_t*)(C + (size_t)(row0 + 8) * N + col) =
                    pack_h2(acc[mt][nt][2], acc[mt][nt][3]);
            } else {
                float* C = (float*)Cv;
                *(float2*)(C + (size_t)row0 * N + col) =
                    make_float2(acc[mt][nt][0], acc[mt][nt][1]);
                *(float2*)(C + (size_t)(row0 + 8) * N + col) =
                    make_float2(acc[mt][nt][2], acc[mt][nt][3]);
            }
        }
    }
}

// ===========================================================================
// Pre-passes
// ===========================================================================
// float -> half elementwise (n4 = count/4)
__global__ __launch_bounds__(256) void conv_half_kernel(
    const float* __restrict__ in, __half* __restrict__ out, size_t n4)
{
    size_t i = (size_t)blockIdx.x * blockDim.x + threadIdx.x;
    size_t stride = (size_t)gridDim.x * blockDim.x;
    for (; i < n4; i += stride) {
        float4 v = ((const float4*)in)[i];
        uint2 o;
        o.x = pack_h2(v.x, v.y);
        o.y = pack_h2(v.z, v.w);
        ((uint2*)out)[i] = o;
    }
}

// out[c][r] = half(in[r][c]); R, C multiples of 32. Block 32x8.
__global__ __launch_bounds__(256) void transpose_h_kernel(
    const float* __restrict__ in, __half* __restrict__ out, int R, int C)
{
    __shared__ float tile[32][33];
    const int bx = blockIdx.x * 32, by = blockIdx.y * 32;
    const int tx = threadIdx.x, ty = threadIdx.y;
    #pragma unroll
    for (int i = 0; i < 32; i += 8)
        tile[ty + i][tx] = in[(size_t)(by + ty + i) * C + bx + tx];
    __syncthreads();
    #pragma unroll
    for (int i = 0; i < 32; i += 8)
        out[(size_t)(bx + ty + i) * R + by + tx] = __float2half_rn(tile[tx][ty + i]);
}

// V transpose (half): g_vTh[c][s] = qkvh[s][2*DIM + c]
__global__ __launch_bounds__(256) void v_transpose_h_kernel(
    const __half* __restrict__ qkvh, __half* __restrict__ vT)
{
    __shared__ __half tile[32][34];
    const int bx = blockIdx.x * 32;   // c block
    const int by = blockIdx.y * 32;   // s block
    const int tx = threadIdx.x, ty = threadIdx.y;
    #pragma unroll
    for (int i = 0; i < 32; i += 8)
        tile[ty + i][tx] = qkvh[(size_t)(by + ty + i) * QKVW + 2 * DIM + bx + tx];
    __syncthreads();
    #pragma unroll
    for (int i = 0; i < 32; i += 8)
        vT[(size_t)(bx + ty + i) * SEQ + by + tx] = tile[tx][ty + i];
}

// ===========================================================================
// Flash attention, fp16 mma. 256 threads (8 warps), 128 queries x 1 head / CTA.
// 3 K+V stages of 32KB (K 64x256B + VT 128x128B), PS 16KB, mbarrier ring.
// smem: 3*32768 + 16384 + 64 = 114752 B
// ===========================================================================
#define FLASH_SMEM 114752

__global__ __launch_bounds__(256, 1) void flash_mma_kernel(
    const __half* __restrict__ qkv, const __half* __restrict__ vT,
    __half* __restrict__ O)
{
    extern __shared__ __align__(1024) char smem[];
    const uint32_t sb  = smem_u32(smem);
    const uint32_t PS  = sb + 98304u;            // 16KB P tile (128 x 128B)
    const uint32_t MB  = sb + 114688u;           // full[s]=MB+8s, empty[s]=MB+24+8s

    const int tid  = threadIdx.x;
    const int lane = tid & 31;
    const int wid  = tid >> 5;
    const int qb   = 31 - blockIdx.x;   // heavy blocks first
    const int h    = blockIdx.y;
    const float scale2 = 0.12751879652672068f;   // (1/sqrt(128)) * log2(e)

    const int a_row16 = lane & 15;
    const int a_ch    = lane >> 4;
    const int b_row   = (lane & 7) + (lane >> 4) * 8;
    const int b_ch    = (lane >> 3) & 1;
    const int g       = lane >> 2;
    const int tg      = lane & 3;

    // ---- Stage Q tile (128 x 128 halves = 256B rows, 32KB) into stage0 region
    {
        const __half* Qg = qkv + (size_t)(qb * 128) * QKVW + h * HD;
        #pragma unroll
        for (int i = 0; i < 8; i++) {
            int slot = i * 256 + tid;
            int r = slot >> 4, c = slot & 15;            // 128 rows x 16 chunks
            cp_async16(swz(sb, r, c, 256), Qg + (size_t)r * QKVW + c * 8);
        }
        asm volatile("cp.async.commit_group;" ::: "memory");
        asm volatile("cp.async.wait_group 0;" ::: "memory");
        __syncthreads();
    }
    uint32_t qf[8][4];
    #pragma unroll
    for (int k16 = 0; k16 < 8; k16++)
        ldsm4(qf[k16][0], qf[k16][1], qf[k16][2], qf[k16][3],
              swz(sb, wid * 16 + a_row16, k16 * 2 + a_ch, 256));
    __syncthreads();   // Q extraction done before stage0 overwritten

    if (tid == 0) {
        #pragma unroll
        for (int s = 0; s < 3; s++) {
            MBARRIER_INIT(MB + 8 * s, 256);        // full[s]
            MBARRIER_INIT(MB + 24 + 8 * s, 256);   // empty[s]
        }
    }
    __syncthreads();

    float oacc[16][4];
    #pragma unroll
    for (int nt = 0; nt < 16; nt++)
        #pragma unroll
        for (int q = 0; q < 4; q++) oacc[nt][q] = 0.f;
    float m0 = -1e30f, m1 = -1e30f, l0 = 0.f, l1 = 0.f;

    const int kb_end = min(2 * qb + 2, 63);   // always >= 2
    const int qi0 = qb * 128 + wid * 16;

    // Load K+V tile t into stage st (8 cp.async per thread)
    auto load_tile = [&](int t, int st) {
        const uint32_t KSb  = sb + (uint32_t)st * 32768u;
        const uint32_t VTSb = KSb + 16384u;
        const __half* Kg = qkv + (size_t)(t * 64) * QKVW + DIM + h * HD;
        const __half* Vg = vT + (size_t)(h * HD) * SEQ + t * 64;
        #pragma unroll
        for (int i = 0; i < 4; i++) {
            int slot = i * 256 + tid;
            int r = slot >> 4, c = slot & 15;            // 64 rows x 16 chunks
            cp_async16(swz(KSb, r, c, 256), Kg + (size_t)r * QKVW + c * 8);
        }
        #pragma unroll
        for (int i = 0; i < 4; i++) {
            int slot = i * 256 + tid;
            int r = slot >> 3, c = slot & 7;             // 128 rows x 8 chunks
            cp_async16(swz(VTSb, r, c, 128), Vg + (size_t)r * SEQ + c * 8);
        }
    };

    // prologue: tiles 0 and 1 (generation 0 — no empty wait needed)
    load_tile(0, 0); CPASYNC_MBAR_ARRIVE(MB + 0);
    load_tile(1, 1); CPASYNC_MBAR_ARRIVE(MB + 8);

    for (int kb = 0; kb <= kb_end; kb++) {
        // ---- producer: tile kb+2 into stage (kb+2)%3
        {
            const int t = kb + 2;
            if (t <= kb_end) {
                const int st = t % 3;
                if (t >= 3)
                    MBARRIER_WAIT_PARITY(MB + 24 + 8 * st, (uint32_t)((t / 3 - 1) & 1));
                load_tile(t, st);
                CPASYNC_MBAR_ARRIVE(MB + 8 * st);
            }
        }

        const int s  = kb % 3;
        const int ph = (kb / 3) & 1;
        MBARRIER_WAIT_PARITY(MB + 8 * s, (uint32_t)ph);   // K+V tile kb resident

        const bool skipw = (kb * 64 > qi0 + 16);   // fully masked for this warp
        if (!skipw) {
            const uint32_t KSb  = sb + (uint32_t)s * 32768u;
            const uint32_t VTSb = KSb + 16384u;

            // ---- S = Q @ K^T  (m16 per warp, n64, k128)
            float sacc[8][4];
            #pragma unroll
            for (int nt = 0; nt < 8; nt++)
                #pragma unroll
                for (int q = 0; q < 4; q++) sacc[nt][q] = 0.f;

            #pragma unroll
            for (int k16 = 0; k16 < 8; k16++) {
                uint32_t bfr[4][4];
                #pragma unroll
                for (int np = 0; np < 4; np++)
                    ldsm4(bfr[np][0], bfr[np][1], bfr[np][2], bfr[np][3],
                          swz(KSb, np * 16 + b_row, k16 * 2 + b_ch, 256));
                #pragma unroll
                for (int nt = 0; nt < 8; nt++) {
                    uint32_t b2[2] = { bfr[nt >> 1][(nt & 1) * 2],
                                       bfr[nt >> 1][(nt & 1) * 2 + 1] };
                    mma_f16(sacc[nt], qf[k16], b2);
                }
            }

            // ---- online softmax in exp2 domain (rows qi0+g, qi0+g+8)
            const int row0 = qi0 + g, row1 = qi0 + g + 8;
            const bool nomask = (kb * 64 + 63 <= qi0 + 1);
            float mx0 = -1e30f, mx1 = -1e30f;
            if (nomask) {
                #pragma unroll
                for (int nt = 0; nt < 8; nt++)
                    #pragma unroll
                    for (int c = 0; c < 2; c++) {
                        float v0 = sacc[nt][c] * scale2;
                        float v1 = sacc[nt][c + 2] * scale2;
                        sacc[nt][c] = v0; sacc[nt][c + 2] = v1;
                        mx0 = fmaxf(mx0, v0); mx1 = fmaxf(mx1, v1);
                    }
            } else {
                #pragma unroll
                for (int nt = 0; nt < 8; nt++)
                    #pragma unroll
                    for (int c = 0; c < 2; c++) {
                        int kj = kb * 64 + nt * 8 + tg * 2 + c;
                        float v0 = (kj <= row0 + 1) ? sacc[nt][c] * scale2 : -1e30f;
                        float v1 = (kj <= row1 + 1) ? sacc[nt][c + 2] * scale2 : -1e30f;
                        sacc[nt][c] = v0; sacc[nt][c + 2] = v1;
                        mx0 = fmaxf(mx0, v0); mx1 = fmaxf(mx1, v1);
                    }
            }
            mx0 = fmaxf(mx0, __shfl_xor_sync(0xffffffffu, mx0, 1));
            mx0 = fmaxf(mx0, __shfl_xor_sync(0xffffffffu, mx0, 2));
            mx1 = fmaxf(mx1, __shfl_xor_sync(0xffffffffu, mx1, 1));
            mx1 = fmaxf(mx1, __shfl_xor_sync(0xffffffffu, mx1, 2));

            float newm0 = fmaxf(m0, mx0), newm1 = fmaxf(m1, mx1);
            float f0 = exp2f(m0 - newm0), f1 = exp2f(m1 - newm1);
            m0 = newm0; m1 = newm1;

            float rs0 = 0.f, rs1 = 0.f;
            #pragma unroll
            for (int nt = 0; nt < 8; nt++)
                #pragma unroll
                for (int c = 0; c < 2; c++) {
                    float p0 = exp2f(sacc[nt][c] - newm0);
                    float p1 = exp2f(sacc[nt][c + 2] - newm1);
                    sacc[nt][c] = p0; sacc[nt][c + 2] = p1;
                    rs0 += p0; rs1 += p1;
                }

            // ---- store P (half) to PS: rows 128B (64 halves)
            {
                const int r0 = wid * 16 + g, r1 = r0 + 8;
                #pragma unroll
                for (int nt = 0; nt < 8; nt++) {
                    uint32_t byte_in = (uint32_t)(tg * 4);
                    asm volatile("st.shared.u32 [%0], %1;"
                        :: "r"(swz(PS, r0, nt, 128) + byte_in),
                           "r"(pack_h2(sacc[nt][0], sacc[nt][1])));
                    asm volatile("st.shared.u32 [%0], %1;"
                        :: "r"(swz(PS, r1, nt, 128) + byte_in),
                           "r"(pack_h2(sacc[nt][2], sacc[nt][3])));
                }
            }
            __syncwarp();

            rs0 += __shfl_xor_sync(0xffffffffu, rs0, 1);
            rs0 += __shfl_xor_sync(0xffffffffu, rs0, 2);
            rs1 += __shfl_xor_sync(0xffffffffu, rs1, 1);
            rs1 += __shfl_xor_sync(0xffffffffu, rs1, 2);
            l0 = l0 * f0 + rs0;
            l1 = l1 * f1 + rs1;

            #pragma unroll
            for (int nt = 0; nt < 16; nt++) {
                oacc[nt][0] *= f0; oacc[nt][1] *= f0;
                oacc[nt][2] *= f1; oacc[nt][3] *= f1;
            }

            // ---- O += P @ V  (m16 per warp, n128, k64)
            #pragma unroll
            for (int k16 = 0; k16 < 4; k16++) {
                uint32_t afr[4];
                ldsm4(afr[0], afr[1], afr[2], afr[3],
                      swz(PS, wid * 16 + a_row16, k16 * 2 + a_ch, 128));
                #pragma unroll
                for (int np = 0; np < 8; np++) {
                    uint32_t bfr[4];
                    ldsm4(bfr[0], bfr[1], bfr[2], bfr[3],
                          swz(VTSb, np * 16 + b_row, k16 * 2 + b_ch, 128));
                    uint32_t b2a[2] = { bfr[0], bfr[1] };
                    uint32_t b2b[2] = { bfr[2], bfr[3] };
                    mma_f16(oacc[np * 2 + 0], afr, b2a);
                    mma_f16(oacc[np * 2 + 1], afr, b2b);
                }
            }
        }

        MBARRIER_ARRIVE(MB + 24 + 8 * s);   // done with stage s this generation
    }

    // ---- epilogue: normalize, store half (GEMM2 consumes fp16)
    const float inv0 = 1.f / l0, inv1 = 1.f / l1;
    const int row0 = qb * 128 + wid * 16 + g;
    __half* Og = O + (size_t)row0 * DIM + h * HD;
    #pragma unroll
    for (int nt = 0; nt < 16; nt++) {
        int col = nt * 8 + tg * 2;
        *(uint32_t*)(Og + col) = pack_h2(oacc[nt][0] * inv0, oacc[nt][1] * inv0);
        *(uint32_t*)(Og + (size_t)8 * DIM + col) =
            pack_h2(oacc[nt][2] * inv1, oacc[nt][3] * inv1);
    }
}

// ===========================================================================
// Launch
// ===========================================================================
extern "C" void kernel_launch(void* const* d_in, const int* in_sizes, int n_in,
                              void* d_out, int out_size)
{
    const float* x     = (const float*)d_in[0];  // (4096, 2048)
    const float* w_qkv = (const float*)d_in[1];  // (2048, 6144)
    const float* w_o   = (const float*)d_in[2];  // (2048, 2048)
    float* out = (float*)d_out;                  // (4096, 2048)

    __half *qkvh, *oh, *xh, *wqkvT, *woT, *vTh;
    cudaGetSymbolAddress((void**)&qkvh,  g_qkvh);
    cudaGetSymbolAddress((void**)&oh,    g_oh);
    cudaGetSymbolAddress((void**)&xh,    g_xh);
    cudaGetSymbolAddress((void**)&wqkvT, g_wqkvT);
    cudaGetSymbolAddress((void**)&woT,   g_woT);
    cudaGetSymbolAddress((void**)&vTh,   g_vTh);

    cudaFuncSetAttribute(gemm_f16_mma<1>,
                         cudaFuncAttributeMaxDynamicSharedMemorySize, GEMM_SMEM);
    cudaFuncSetAttribute(gemm_f16_mma<0>,
                         cudaFuncAttributeMaxDynamicSharedMemorySize, GEMM_SMEM);
    cudaFuncSetAttribute(flash_mma_kernel,
                         cudaFuncAttributeMaxDynamicSharedMemorySize, FLASH_SMEM);

    // 0) convert x; transpose+convert weights
    conv_half_kernel<<<2048, 256>>>(x, xh, (size_t)SEQ * DIM / 4);
    transpose_h_kernel<<<dim3(QKVW / 32, DIM / 32), dim3(32, 8)>>>(w_qkv, wqkvT, DIM, QKVW);
    transpose_h_kernel<<<dim3(DIM / 32, DIM / 32), dim3(32, 8)>>>(w_o, woT, DIM, DIM);

    // 1) QKV projection (fp16 mma, half output)
    gemm_f16_mma<1><<<dim3(QKVW / 128, SEQ / 128), 256, GEMM_SMEM>>>(
        xh, wqkvT, qkvh, SEQ, QKVW, DIM);

    // 1b) transpose V per head
    v_transpose_h_kernel<<<dim3(DIM / 32, SEQ / 32), dim3(32, 8)>>>(qkvh, vTh);

    // 2) Attention (fp16 mma flash)
    flash_mma_kernel<<<dim3(SEQ / 128, NH), 256, FLASH_SMEM>>>(qkvh, vTh, oh);

    // 3) Output projection (fp16 mma, float output)
    gemm_f16_mma<0><<<dim3(DIM / 128, SEQ / 128), 256, GEMM_SMEM>>>(
        oh, woT, out, SEQ, DIM, DIM);
}